// round 12
// baseline (speedup 1.0000x reference)
#include <cuda_runtime.h>
#include <math.h>

#define NB 512
#define NN 128
#define CORR_LIM 2048
#define CAND_CAP (NB * 3 * NN)
#define NEG_INF -3e38f
#define NBINS_A 2048
#define BIAS_A  0x3D00
#define BINBUF_CAP 65536
#define K3B 64

// ---------------- device scratch ----------------
__device__ float        g_cand_val[CAND_CAP];
__device__ int          g_cand_idx[CAND_CAP];
__device__ int          g_cand_cnt;
__device__ int          g_bin;
__device__ int          g_G16;
__device__ int          g_kk;
__device__ int          g_gt_ctr;
__device__ float        g_binval[BINBUF_CAP];
__device__ int          g_binidx[BINBUF_CAP];
__device__ int          g_bincnt;
__device__ float        g_localT[NB * 12];
__device__ int          g_pc[NB];
__device__ int          g_best_key;
__device__ float        g_sel_score[CORR_LIM];
__device__ float        g_sel_src[CORR_LIM * 3];
__device__ float        g_sel_ref[CORR_LIM * 3];
__device__ int          g_k1done, g_k3done, g_k4done;
__device__ unsigned char g_refm[NB * NN];
__device__ unsigned char g_srcm[NB * NN];

// ---------------- f32 Kabsch ----------------
__device__ inline float det3f(const float* M) {
    return M[0]*(M[4]*M[8]-M[5]*M[7])
         - M[1]*(M[3]*M[8]-M[5]*M[6])
         + M[2]*(M[3]*M[7]-M[4]*M[6]);
}

__device__ void jacobi3f(float A[9], float V[9]) {
    for (int i = 0; i < 9; i++) V[i] = (i % 4 == 0) ? 1.0f : 0.0f;
    float fro = fabsf(A[0]) + fabsf(A[4]) + fabsf(A[8]) + 1e-30f;
    for (int sweep = 0; sweep < 10; sweep++) {
        float off = fabsf(A[1]) + fabsf(A[2]) + fabsf(A[5]);
        if (off < fro * 1e-7f + 1e-35f) break;
        for (int pq = 0; pq < 3; pq++) {
            int p = (pq == 2) ? 1 : 0;
            int q = (pq == 0) ? 1 : 2;
            float apq = A[p*3+q];
            if (fabsf(apq) < 1e-35f) continue;
            float theta = (A[q*3+q] - A[p*3+p]) / (2.0f * apq);
            float tt = ((theta >= 0.0f) ? 1.0f : -1.0f) / (fabsf(theta) + sqrtf(1.0f + theta*theta));
            float c = rsqrtf(1.0f + tt*tt);
            float s = tt * c;
            for (int k = 0; k < 3; k++) {
                float akp = A[k*3+p], akq = A[k*3+q];
                A[k*3+p] = c*akp - s*akq;
                A[k*3+q] = s*akp + c*akq;
            }
            for (int k = 0; k < 3; k++) {
                float apk = A[p*3+k], aqk = A[q*3+k];
                A[p*3+k] = c*apk - s*aqk;
                A[q*3+k] = s*apk + c*aqk;
            }
            for (int k = 0; k < 3; k++) {
                float vkp = V[k*3+p], vkq = V[k*3+q];
                V[k*3+p] = c*vkp - s*vkq;
                V[k*3+q] = s*vkp + c*vkq;
            }
        }
    }
}

__device__ void kabschf(const float H[9], float R[9]) {
    float A[9];
    for (int i = 0; i < 3; i++)
        for (int j = 0; j < 3; j++)
            A[i*3+j] = H[0+i]*H[0+j] + H[3+i]*H[3+j] + H[6+i]*H[6+j];

    float V[9];
    jacobi3f(A, V);
    float e0 = A[0], e1 = A[4], e2 = A[8];
    int o0 = 0, o1 = 1, o2 = 2;
    float t; int ti;
    if (e0 < e1) { t = e0; e0 = e1; e1 = t; ti = o0; o0 = o1; o1 = ti; }
    if (e0 < e2) { t = e0; e0 = e2; e2 = t; ti = o0; o0 = o2; o2 = ti; }
    if (e1 < e2) { t = e1; e1 = e2; e2 = t; ti = o1; o1 = o2; o2 = ti; }
    float Vs[9];
    int ord[3] = {o0, o1, o2};
    for (int r = 0; r < 3; r++)
        for (int k = 0; k < 3; k++)
            Vs[r*3+k] = V[r*3+ord[k]];

    float u[3][3];
    for (int i = 0; i < 2; i++)
        for (int r = 0; r < 3; r++)
            u[i][r] = H[r*3+0]*Vs[0*3+i] + H[r*3+1]*Vs[1*3+i] + H[r*3+2]*Vs[2*3+i];
    float n0 = sqrtf(u[0][0]*u[0][0] + u[0][1]*u[0][1] + u[0][2]*u[0][2]) + 1e-30f;
    for (int r = 0; r < 3; r++) u[0][r] /= n0;
    float dp = u[1][0]*u[0][0] + u[1][1]*u[0][1] + u[1][2]*u[0][2];
    for (int r = 0; r < 3; r++) u[1][r] -= dp * u[0][r];
    float n1 = sqrtf(u[1][0]*u[1][0] + u[1][1]*u[1][1] + u[1][2]*u[1][2]) + 1e-30f;
    for (int r = 0; r < 3; r++) u[1][r] /= n1;
    u[2][0] = u[0][1]*u[1][2] - u[0][2]*u[1][1];
    u[2][1] = u[0][2]*u[1][0] - u[0][0]*u[1][2];
    u[2][2] = u[0][0]*u[1][1] - u[0][1]*u[1][0];

    float d = (det3f(Vs) >= 0.0f) ? 1.0f : -1.0f;
    for (int i = 0; i < 3; i++)
        for (int j = 0; j < 3; j++)
            R[i*3+j] = Vs[i*3+0]*u[0][j] + Vs[i*3+1]*u[1][j] + Vs[i*3+2]*d*u[2][j];
}

__device__ void solveTf(const float* P, float R[9], float tv[3]) {
    float denom = P[0] + 1e-5f;
    float sc[3] = {P[1]/denom, P[2]/denom, P[3]/denom};
    float rc[3] = {P[4]/denom, P[5]/denom, P[6]/denom};
    float W = P[0] / denom;
    float H[9];
    for (int c = 0; c < 3; c++)
        for (int d = 0; d < 3; d++)
            H[c*3+d] = P[7 + c*3 + d] / denom + (W - 2.0f) * sc[c] * rc[d];
    kabschf(H, R);
    for (int i = 0; i < 3; i++)
        tv[i] = rc[i] - (R[i*3+0]*sc[0] + R[i*3+1]*sc[1] + R[i*3+2]*sc[2]);
}

// ---------------- branchless sorted-triple ops ----------------
__device__ __forceinline__ void ins3(float& c1, float& c2, float& c3, float v) {
    float t1 = fmaxf(c1, v),  d1 = fminf(c1, v);
    float t2 = fmaxf(c2, d1), d2 = fminf(c2, d1);
    c3 = fmaxf(c3, d2); c2 = t2; c1 = t1;
}
__device__ __forceinline__ void merge3(float& a1, float& a2, float& a3,
                                       float b1, float b2, float b3) {
    float c1 = fmaxf(a1, b1);
    float p  = fminf(a1, b1);
    float q  = fmaxf(a2, b2);
    float r  = fminf(a2, b2);
    float c2 = fmaxf(p, q);
    float c3 = fmaxf(fminf(p, q), fmaxf(r, fmaxf(a3, b3)));
    a1 = c1; a2 = c2; a3 = c3;
}

// ---------------- mask handling ----------------
__device__ inline unsigned char fetch_mask(const void* p, int i, int ty) {
    switch (ty) {
        case 0:  return ((const unsigned char*)p)[i] != 0;
        case 1:  return ((const int*)p)[i] != 0;
        case 2:  return ((const unsigned int*)p)[i] != 0;
        default: return ((const unsigned short*)p)[i] != 0;
    }
}

__device__ int detect_mask_type(const unsigned char* p, int t, int* cnts) {
    int l3 = 0, l1 = 0, o1 = 0;
    #pragma unroll
    for (int j = 0; j < 4; j++) {
        int i = t * 4 + j;
        unsigned char bch = p[i];
        int m = i & 3;
        if (bch == 0x3F) { if (m == 3) l3++; else if (m == 1) l1++; }
        if (bch == 0x01 && (i & 1)) o1++;
    }
    if (l3) atomicAdd(&cnts[0], l3);
    if (l1) atomicAdd(&cnts[1], l1);
    if (o1) atomicAdd(&cnts[2], o1);
    __syncthreads();
    if (cnts[1] > 8)      return 3;   // bf16
    else if (cnts[0] > 8) return 2;   // f32
    else if (cnts[2] > 8) return 0;   // u8/bool
    return 1;                          // i32
}

__global__ void k_norm_init(const void* m0, const void* m1) {
    __shared__ int s_cnts[6];
    int t = threadIdx.x;
    int i = blockIdx.x * blockDim.x + t;
    if (t < 6) s_cnts[t] = 0;
    __syncthreads();
    int tyr = detect_mask_type((const unsigned char*)m0, t, &s_cnts[0]);
    int tys = detect_mask_type((const unsigned char*)m1, t, &s_cnts[3]);

    if (i < CORR_LIM) g_sel_score[i] = 0.0f;
    if (i == 0) {
        g_cand_cnt = 0; g_gt_ctr = 0; g_bincnt = 0;
        g_best_key = 0; g_bin = -1;   g_G16 = 0;  g_kk = 0;
        g_k1done = 0;   g_k3done = 0; g_k4done = 0;
    }
    if (i < NB * NN) {
        g_refm[i] = fetch_mask(m0, i, tyr);
        g_srcm[i] = fetch_mask(m1, i, tys);
    }
}

// -------- two-phase cooperative descending k-select over NBINS bins --------
template<int NBINS>
__device__ void find_binT(const unsigned int* hist, int k,
                          int* out_bin, int* out_above, int* out_rem)
{
    const int CH = NBINS / 256;
    __shared__ unsigned int wsum[8];
    __shared__ unsigned int woff[8];
    __shared__ int s_tb;
    __shared__ unsigned int s_excl;
    int t = threadIdx.x, lane = t & 31, w = t >> 5;

    int base = NBINS - CH * (t + 1);
    unsigned int sum = 0;
    const uint4* hv = (const uint4*)(hist + base);
    #pragma unroll 2
    for (int j = 0; j < CH / 4; j++) {
        uint4 u = hv[j];
        sum += u.x + u.y + u.z + u.w;
    }
    unsigned int sc = sum;
    #pragma unroll
    for (int off = 1; off < 32; off <<= 1) {
        unsigned int v = __shfl_up_sync(0xffffffffu, sc, off);
        if (lane >= off) sc += v;
    }
    if (lane == 31) wsum[w] = sc;
    __syncthreads();
    if (t == 0) {
        unsigned int acc = 0;
        #pragma unroll
        for (int j = 0; j < 8; j++) { woff[j] = acc; acc += wsum[j]; }
    }
    __syncthreads();
    unsigned int incl = sc + woff[w];
    unsigned int excl = incl - sum;
    if (incl >= (unsigned int)k && excl < (unsigned int)k) { s_tb = t; s_excl = excl; }
    __syncthreads();

    int tb = s_tb;
    unsigned int excl_c = s_excl;
    int chunk_top = NBINS - 1 - CH * tb;
    unsigned int h2 = (t < CH) ? hist[chunk_top - t] : 0u;
    unsigned int sc2 = h2;
    #pragma unroll
    for (int off = 1; off < 32; off <<= 1) {
        unsigned int v = __shfl_up_sync(0xffffffffu, sc2, off);
        if (lane >= off) sc2 += v;
    }
    __syncthreads();
    if (lane == 31) wsum[w] = sc2;
    __syncthreads();
    if (t == 0) {
        unsigned int acc = 0;
        #pragma unroll
        for (int j = 0; j < 8; j++) { woff[j] = acc; acc += wsum[j]; }
    }
    __syncthreads();
    unsigned int incl2 = excl_c + sc2 + woff[w];
    unsigned int excl2 = incl2 - h2;
    if (t < CH && incl2 >= (unsigned int)k && excl2 < (unsigned int)k) {
        *out_bin = chunk_top - t;
        *out_above = (int)excl2;
        *out_rem = k - (int)excl2;
    }
}

// ------ cooperative descending k-select over 256 smem bins (1 bin/thread) ----
__device__ void find256(const unsigned int* h, int k, int* out_bin, int* out_above)
{
    __shared__ unsigned int wsum2[8];
    __shared__ unsigned int woff2[8];
    int t = threadIdx.x, lane = t & 31, w = t >> 5;
    unsigned int val = h[255 - t];
    unsigned int sc = val;
    #pragma unroll
    for (int off = 1; off < 32; off <<= 1) {
        unsigned int v = __shfl_up_sync(0xffffffffu, sc, off);
        if (lane >= off) sc += v;
    }
    if (lane == 31) wsum2[w] = sc;
    __syncthreads();
    if (t == 0) {
        unsigned int acc = 0;
        #pragma unroll
        for (int j = 0; j < 8; j++) { woff2[j] = acc; acc += wsum2[j]; }
    }
    __syncthreads();
    unsigned int incl = sc + woff2[w];
    unsigned int excl = incl - val;
    if (incl >= (unsigned int)k && excl < (unsigned int)k) {
        *out_bin = 255 - t;
        *out_above = (int)excl;
    }
    __syncthreads();
}

// ----- k1: single-read fused per-batch kernel + last-block level-1 select ---
__global__ void __launch_bounds__(256)
k1_batch(const float* __restrict__ score,
         const float* __restrict__ refp,
         const float* __restrict__ srcp)
{
    __shared__ float colpart[8][NN][3];
    __shared__ float colth[NN];
    __shared__ float candv[NN * 4];
    __shared__ int   candcol[NN * 4];
    __shared__ int   candc[NN];
    __shared__ unsigned char s_srcm[NN], s_refm[NN];
    __shared__ float wred[8][17];
    __shared__ int   wcnt[8];
    __shared__ int   s_base;
    __shared__ int   s_last;

    int b = blockIdx.x, t = threadIdx.x;
    int w = t >> 5, lane = t & 31;
    const float* Sb = score + (size_t)b * (NN * NN);

    if (t < NN) { s_srcm[t] = g_srcm[b*NN + t]; s_refm[t] = g_refm[b*NN + t]; }
    if (lane < 16) candc[w * 16 + lane] = 0;
    __syncwarp();

    float c1x = NEG_INF, c2x = NEG_INF, c3x = NEG_INF;
    float c1y = NEG_INF, c2y = NEG_INF, c3y = NEG_INF;
    float c1z = NEG_INF, c2z = NEG_INF, c3z = NEG_INF;
    float c1w = NEG_INF, c2w = NEG_INF, c3w = NEG_INF;

    #pragma unroll 1
    for (int i = 0; i < 16; i++) {
        int r = (w << 4) + i;
        float4 v4 = *(const float4*)(Sb + r * NN + lane * 4);

        ins3(c1x, c2x, c3x, v4.x);
        ins3(c1y, c2y, c3y, v4.y);
        ins3(c1z, c2z, c3z, v4.z);
        ins3(c1w, c2w, c3w, v4.w);

        float s1 = fmaxf(v4.x, v4.y), s2 = fminf(v4.x, v4.y);
        float s3 = fmaxf(v4.z, v4.w), s4 = fminf(v4.z, v4.w);
        float a1 = fmaxf(s1, s3),     m  = fminf(s1, s3);
        float tq = fmaxf(s2, s4),     bo = fminf(s2, s4);
        float a2 = fmaxf(m, tq);
        float a3 = fmaxf(fminf(m, tq), bo);

        #pragma unroll
        for (int off = 16; off; off >>= 1) {
            float b1 = __shfl_xor_sync(0xffffffffu, a1, off);
            float b2 = __shfl_xor_sync(0xffffffffu, a2, off);
            float b3 = __shfl_xor_sync(0xffffffffu, a3, off);
            merge3(a1, a2, a3, b1, b2, b3);
        }

        float vv[4] = {v4.x, v4.y, v4.z, v4.w};
        #pragma unroll
        for (int j = 0; j < 4; j++) {
            if (vv[j] >= a3) {
                int pos = atomicAdd(&candc[r], 1);
                if (pos < 4) {
                    candv[r*4 + pos]   = vv[j];
                    candcol[r*4 + pos] = lane * 4 + j;
                }
            }
        }
    }
    {
        int cbase = lane * 4;
        colpart[w][cbase+0][0] = c1x; colpart[w][cbase+0][1] = c2x; colpart[w][cbase+0][2] = c3x;
        colpart[w][cbase+1][0] = c1y; colpart[w][cbase+1][1] = c2y; colpart[w][cbase+1][2] = c3y;
        colpart[w][cbase+2][0] = c1z; colpart[w][cbase+2][1] = c2z; colpart[w][cbase+2][2] = c3z;
        colpart[w][cbase+3][0] = c1w; colpart[w][cbase+3][1] = c2w; colpart[w][cbase+3][2] = c3w;
    }
    __syncthreads();

    if (t < NN) {
        float m1 = colpart[0][t][0], m2 = colpart[0][t][1], m3 = colpart[0][t][2];
        #pragma unroll
        for (int w2 = 1; w2 < 8; w2++)
            merge3(m1, m2, m3, colpart[w2][t][0], colpart[w2][t][1], colpart[w2][t][2]);
        colth[t] = m3;
    }
    __syncthreads();

    bool  ok[2];
    float ev[2];
    int   rr[2], cs2[2];
    int myc = 0;
    #pragma unroll
    for (int k2 = 0; k2 < 2; k2++) {
        int idx = t + k2 * 256;
        int r = idx >> 2, kk = idx & 3;
        bool good = false; float e = 0.0f; int ss = 0;
        int cc = candc[r]; if (cc > 4) cc = 4;
        if (kk < cc && s_refm[r]) {
            float v = candv[idx];
            ss = candcol[idx];
            if (v >= colth[ss] && s_srcm[ss]) {
                e = expf(v);
                if (e > 0.05f) good = true;
            }
        }
        ok[k2] = good; ev[k2] = e; rr[k2] = r; cs2[k2] = ss;
        if (good) myc++;
    }

    int pfx = myc;
    #pragma unroll
    for (int off = 1; off < 32; off <<= 1) {
        int nv = __shfl_up_sync(0xffffffffu, pfx, off);
        if (lane >= off) pfx += nv;
    }
    if (lane == 31) wcnt[w] = pfx;
    __syncthreads();
    if (t == 0) {
        int tot = 0;
        for (int w2 = 0; w2 < 8; w2++) { int c = wcnt[w2]; wcnt[w2] = tot; tot += c; }
        s_base = tot ? atomicAdd(&g_cand_cnt, tot) : 0;
    }
    __syncthreads();
    int pos = s_base + wcnt[w] + (pfx - myc);

    float P[16];
    #pragma unroll
    for (int j = 0; j < 16; j++) P[j] = 0.0f;
    #pragma unroll
    for (int k2 = 0; k2 < 2; k2++) {
        if (!ok[k2]) continue;
        float e = ev[k2];
        int r = rr[k2], ss = cs2[k2];
        g_cand_val[pos] = e;
        g_cand_idx[pos] = (b << 14) | (r << 7) | ss;
        pos++;
        float sx = srcp[(b*NN + ss)*3 + 0];
        float sy = srcp[(b*NN + ss)*3 + 1];
        float sz = srcp[(b*NN + ss)*3 + 2];
        float rx = refp[(b*NN + r)*3 + 0];
        float ry = refp[(b*NN + r)*3 + 1];
        float rz = refp[(b*NN + r)*3 + 2];
        P[0] += e;
        P[1] += e*sx; P[2] += e*sy; P[3] += e*sz;
        P[4] += e*rx; P[5] += e*ry; P[6] += e*rz;
        P[7]  += e*sx*rx; P[8]  += e*sx*ry; P[9]  += e*sx*rz;
        P[10] += e*sy*rx; P[11] += e*sy*ry; P[12] += e*sy*rz;
        P[13] += e*sz*rx; P[14] += e*sz*ry; P[15] += e*sz*rz;
    }

    #pragma unroll
    for (int j = 0; j < 16; j++) {
        float v = P[j];
        #pragma unroll
        for (int off = 16; off; off >>= 1) v += __shfl_xor_sync(0xffffffffu, v, off);
        if (lane == 0) wred[w][j] = v;
    }
    {
        int c = myc;
        #pragma unroll
        for (int off = 16; off; off >>= 1) c += __shfl_xor_sync(0xffffffffu, c, off);
        if (lane == 0) wred[w][16] = (float)c;
    }
    __syncthreads();

    if (t == 0) {
        float Pf[16]; int cnt = 0;
        for (int j = 0; j < 16; j++) {
            float acc = 0.0f;
            for (int w2 = 0; w2 < 8; w2++) acc += wred[w2][j];
            Pf[j] = acc;
        }
        for (int w2 = 0; w2 < 8; w2++) cnt += (int)wred[w2][16];
        float R[9], tv[3];
        solveTf(Pf, R, tv);
        for (int j = 0; j < 9; j++) g_localT[b*12 + j] = R[j];
        for (int j = 0; j < 3; j++) g_localT[b*12 + 9 + j] = tv[j];
        g_pc[b] = cnt;
    }

    // ---- last block: build 2048-bin smem histogram over all candidates and
    //      find the level-1 boundary bin (tail work only) ----
    if (t == 0) {
        __threadfence();
        s_last = (atomicAdd(&g_k1done, 1) == NB - 1);
    }
    __syncthreads();
    if (!s_last) return;

    __shared__ __align__(16) unsigned int hist[NBINS_A];
    int M = atomicAdd(&g_cand_cnt, 0); if (M > CAND_CAP) M = CAND_CAP;
    if (M <= CORR_LIM) return;   // g_bin stays -1: take everything

    for (int i = t; i < NBINS_A; i += 256) hist[i] = 0u;
    __syncthreads();
    for (int base2 = 0; base2 < M; base2 += 256) {
        int i = base2 + t;
        if (i < M) {
            unsigned int v = __float_as_uint(__ldcg(&g_cand_val[i]));
            int bb = (int)(v >> 16) - BIAS_A;
            bb = bb < 0 ? 0 : (bb > NBINS_A-1 ? NBINS_A-1 : bb);
            unsigned int am = __activemask();
            unsigned int mm = __match_any_sync(am, bb);
            if ((t & 31) == __ffs(mm) - 1)
                atomicAdd(&hist[bb], (unsigned int)__popc(mm));
        }
    }
    __syncthreads();
    find_binT<NBINS_A>(hist, CORR_LIM, &g_bin, &g_G16, &g_kk);
}

// ------ k3: gather winners (grid-stride, warp-agg) + last-block select ------
__global__ void __launch_bounds__(256)
k3_gather(const float* __restrict__ refp, const float* __restrict__ srcp)
{
    __shared__ int s_last;
    int M = g_cand_cnt;
    if (M > CAND_CAP) M = CAND_CAP;
    int t = threadIdx.x, lane = t & 31;
    int bin = g_bin;

    for (int base = blockIdx.x * 256; base < M; base += K3B * 256) {
        int i = base + t;
        bool valid = (i < M);
        float v = 0.0f; int bb = -1;
        if (valid) {
            v = g_cand_val[i];
            bb = (int)(__float_as_uint(v) >> 16) - BIAS_A;
            bb = bb < 0 ? 0 : (bb > NBINS_A-1 ? NBINS_A-1 : bb);
        }

        bool win = valid && (bin < 0 || bb > bin);
        {
            unsigned int wm = __ballot_sync(0xffffffffu, win);
            if (wm) {
                int leader = __ffs(wm) - 1;
                int sbase = 0;
                if (lane == leader) sbase = atomicAdd(&g_gt_ctr, __popc(wm));
                sbase = __shfl_sync(0xffffffffu, sbase, leader);
                if (win) {
                    int slot = sbase + __popc(wm & ((1u << lane) - 1u));
                    if (slot < CORR_LIM) {
                        int idx = g_cand_idx[i];
                        int b = idx >> 14, r = (idx >> 7) & 127, s = idx & 127;
                        g_sel_score[slot] = v;
                        g_sel_src[slot*3+0] = srcp[(b*NN + s)*3 + 0];
                        g_sel_src[slot*3+1] = srcp[(b*NN + s)*3 + 1];
                        g_sel_src[slot*3+2] = srcp[(b*NN + s)*3 + 2];
                        g_sel_ref[slot*3+0] = refp[(b*NN + r)*3 + 0];
                        g_sel_ref[slot*3+1] = refp[(b*NN + r)*3 + 1];
                        g_sel_ref[slot*3+2] = refp[(b*NN + r)*3 + 2];
                    }
                }
            }
        }
        bool eq = valid && (bin >= 0) && (bb == bin);
        {
            unsigned int wm = __ballot_sync(0xffffffffu, eq);
            if (wm) {
                int leader = __ffs(wm) - 1;
                int sbase = 0;
                if (lane == leader) sbase = atomicAdd(&g_bincnt, __popc(wm));
                sbase = __shfl_sync(0xffffffffu, sbase, leader);
                if (eq) {
                    int j = sbase + __popc(wm & ((1u << lane) - 1u));
                    if (j < BINBUF_CAP) {
                        g_binval[j] = v;
                        g_binidx[j] = g_cand_idx[i];
                    }
                }
            }
        }
    }

    if (t == 0) {
        __threadfence();
        s_last = (atomicAdd(&g_k3done, 1) == K3B - 1);
    }
    __syncthreads();
    if (!s_last || bin < 0) return;

    // ---- last block: exact top-kk within the boundary bin (two 256-bin
    //      smem passes over the low 16 bits) ----
    __shared__ unsigned int hh[256];
    __shared__ int s_sub1, s_above1, s_sub2, s_above2;
    __shared__ int ctrA, ctrB;
    int B = atomicAdd(&g_bincnt, 0); if (B > BINBUF_CAP) B = BINBUF_CAP;
    int kk = g_kk, G16 = g_G16;
    if (t == 0) { ctrA = 0; ctrB = 0; }

    hh[t] = 0u;
    __syncthreads();
    for (int q = t; q < B; q += 256) {
        unsigned int b1 = (__float_as_uint(__ldcg(&g_binval[q])) >> 8) & 0xFFu;
        unsigned int am = __activemask();
        unsigned int mm = __match_any_sync(am, b1);
        if ((t & 31) == __ffs(mm) - 1)
            atomicAdd(&hh[b1], (unsigned int)__popc(mm));
    }
    __syncthreads();
    find256(hh, kk, &s_sub1, &s_above1);
    __syncthreads();
    int SUB1 = s_sub1, ABOVE1 = s_above1;
    int rem1 = kk - ABOVE1;

    hh[t] = 0u;
    __syncthreads();
    for (int q = t; q < B; q += 256) {
        unsigned int lo = __float_as_uint(__ldcg(&g_binval[q])) & 0xFFFFu;
        if ((int)(lo >> 8) == SUB1) {
            unsigned int b2 = lo & 0xFFu;
            unsigned int am = __activemask();
            unsigned int mm = __match_any_sync(am, b2);
            if ((t & 31) == __ffs(mm) - 1)
                atomicAdd(&hh[b2], (unsigned int)__popc(mm));
        }
    }
    __syncthreads();
    find256(hh, rem1, &s_sub2, &s_above2);
    __syncthreads();
    int TH = (SUB1 << 8) | s_sub2;
    int LA = ABOVE1 + s_above2;
    int nties = rem1 - s_above2;

    for (int q = t; q < B; q += 256) {
        float vv = __ldcg(&g_binval[q]);
        int low = (int)(__float_as_uint(vv) & 0xFFFFu);
        int slot = -1;
        if (low > TH) {
            slot = G16 + atomicAdd(&ctrA, 1);
        } else if (low == TH) {
            int e = atomicAdd(&ctrB, 1);
            if (e < nties) slot = G16 + LA + e;
        }
        if (slot >= 0 && slot < CORR_LIM) {
            int idx = __ldcg(&g_binidx[q]);
            int b = idx >> 14, r = (idx >> 7) & 127, s = idx & 127;
            g_sel_score[slot] = vv;
            g_sel_src[slot*3+0] = srcp[(b*NN + s)*3 + 0];
            g_sel_src[slot*3+1] = srcp[(b*NN + s)*3 + 1];
            g_sel_src[slot*3+2] = srcp[(b*NN + s)*3 + 2];
            g_sel_ref[slot*3+0] = refp[(b*NN + r)*3 + 0];
            g_sel_ref[slot*3+1] = refp[(b*NN + r)*3 + 1];
            g_sel_ref[slot*3+2] = refp[(b*NN + r)*3 + 2];
        }
    }
}

// ------- k45: inlier counts + packed argmax + last-block refine -------
__global__ void __launch_bounds__(256)
k45(float* __restrict__ out)
{
    __shared__ int rc_[8];
    __shared__ int s_last;
    int p = blockIdx.x, t = threadIdx.x;
    int w = t >> 5, lane = t & 31;
    {
        const float* LT = &g_localT[p * 12];
        float R0 = LT[0], R1 = LT[1], R2 = LT[2];
        float R3 = LT[3], R4 = LT[4], R5 = LT[5];
        float R6 = LT[6], R7 = LT[7], R8 = LT[8];
        float t0 = LT[9], t1 = LT[10], t2 = LT[11];
        int c = 0;
        for (int i = t; i < CORR_LIM; i += 256) {
            float sv = g_sel_score[i];
            if (sv <= 0.0f) continue;
            float sx = g_sel_src[i*3+0], sy = g_sel_src[i*3+1], sz = g_sel_src[i*3+2];
            float rx = g_sel_ref[i*3+0], ry = g_sel_ref[i*3+1], rz = g_sel_ref[i*3+2];
            float ax = R0*sx + R1*sy + R2*sz + t0;
            float ay = R3*sx + R4*sy + R5*sz + t1;
            float az = R6*sx + R7*sy + R8*sz + t2;
            float dx = rx - ax, dy = ry - ay, dz = rz - az;
            if (dx*dx + dy*dy + dz*dz < 0.01f) c++;
        }
        #pragma unroll
        for (int off = 16; off; off >>= 1) c += __shfl_xor_sync(0xffffffffu, c, off);
        if (lane == 0) rc_[w] = c;
        __syncthreads();
        if (t == 0) {
            int total = 0;
            for (int j = 0; j < 8; j++) total += rc_[j];
            int cnt = (g_pc[p] >= 3) ? total : -1;
            int key = ((cnt + 1) << 16) | (NB - 1 - p);
            atomicMax(&g_best_key, key);
            __threadfence();
            s_last = (atomicAdd(&g_k4done, 1) == NB - 1);
        }
        __syncthreads();
    }
    if (!s_last) return;

    __shared__ float red[8][16];
    __shared__ float Tr[9], Tt[3];
    if (t == 0) {
        int bk = atomicAdd(&g_best_key, 0);
        int bb = NB - 1 - (bk & 0xFFFF);
        for (int j = 0; j < 9; j++) Tr[j] = g_localT[bb*12 + j];
        for (int j = 0; j < 3; j++) Tt[j] = g_localT[bb*12 + 9 + j];
    }
    __syncthreads();

    float lsv[8], lsx[8], lsy[8], lsz[8], lrx[8], lry[8], lrz[8];
    #pragma unroll
    for (int j = 0; j < 8; j++) {
        int i = t + j * 256;
        lsv[j] = g_sel_score[i];
        lsx[j] = g_sel_src[i*3+0]; lsy[j] = g_sel_src[i*3+1]; lsz[j] = g_sel_src[i*3+2];
        lrx[j] = g_sel_ref[i*3+0]; lry[j] = g_sel_ref[i*3+1]; lrz[j] = g_sel_ref[i*3+2];
    }

    unsigned int prev_mask = 0u;
    for (int it = 0; it < 5; it++) {
        float P[16];
        #pragma unroll
        for (int j = 0; j < 16; j++) P[j] = 0.0f;
        unsigned int cur_mask = 0u;
        #pragma unroll
        for (int j = 0; j < 8; j++) {
            float sv = lsv[j];
            if (sv <= 0.0f) continue;
            float sx = lsx[j], sy = lsy[j], sz = lsz[j];
            float rx = lrx[j], ry = lry[j], rz = lrz[j];
            float ax = Tr[0]*sx + Tr[1]*sy + Tr[2]*sz + Tt[0];
            float ay = Tr[3]*sx + Tr[4]*sy + Tr[5]*sz + Tt[1];
            float az = Tr[6]*sx + Tr[7]*sy + Tr[8]*sz + Tt[2];
            float dx = rx - ax, dy = ry - ay, dz = rz - az;
            if (dx*dx + dy*dy + dz*dz < 0.01f) {
                cur_mask |= (1u << j);
                P[0] += sv;
                P[1] += sv*sx; P[2] += sv*sy; P[3] += sv*sz;
                P[4] += sv*rx; P[5] += sv*ry; P[6] += sv*rz;
                P[7]  += sv*sx*rx; P[8]  += sv*sx*ry; P[9]  += sv*sx*rz;
                P[10] += sv*sy*rx; P[11] += sv*sy*ry; P[12] += sv*sy*rz;
                P[13] += sv*sz*rx; P[14] += sv*sz*ry; P[15] += sv*sz*rz;
            }
        }
        int same = __syncthreads_and((it > 0) && (cur_mask == prev_mask));
        if (same) break;
        prev_mask = cur_mask;

        #pragma unroll
        for (int j = 0; j < 16; j++) {
            float v = P[j];
            #pragma unroll
            for (int off = 16; off; off >>= 1) v += __shfl_xor_sync(0xffffffffu, v, off);
            if (lane == 0) red[w][j] = v;
        }
        __syncthreads();
        if (t == 0) {
            float Pf[16];
            for (int j = 0; j < 16; j++) {
                float acc = 0.0f;
                for (int w2 = 0; w2 < 8; w2++) acc += red[w2][j];
                Pf[j] = acc;
            }
            float R[9], tv[3];
            solveTf(Pf, R, tv);
            for (int j = 0; j < 9; j++) Tr[j] = R[j];
            for (int j = 0; j < 3; j++) Tt[j] = tv[j];
        }
        __syncthreads();
    }

    if (t == 0) {
        out[0]  = Tr[0]; out[1]  = Tr[1]; out[2]  = Tr[2]; out[3]  = Tt[0];
        out[4]  = Tr[3]; out[5]  = Tr[4]; out[6]  = Tr[5]; out[7]  = Tt[1];
        out[8]  = Tr[6]; out[9]  = Tr[7]; out[10] = Tr[8]; out[11] = Tt[2];
        out[12] = 0.0f; out[13] = 0.0f; out[14] = 0.0f; out[15] = 1.0f;
    }
}

// ---------------- launch ----------------
extern "C" void kernel_launch(void* const* d_in, const int* in_sizes, int n_in,
                              void* d_out, int out_size)
{
    const float* score = 0;
    const float* refp = 0;  const float* srcp = 0;
    const void*  refm = 0;  const void*  srcm = 0;
    for (int i = 0; i < n_in; i++) {
        int sz = in_sizes[i];
        if (sz == NB * NN * NN) {
            score = (const float*)d_in[i];
        } else if (sz == NB * NN * 3) {
            if (!refp) refp = (const float*)d_in[i];
            else       srcp = (const float*)d_in[i];
        } else if (sz == NB * NN) {
            if (!refm) refm = d_in[i];
            else       srcm = d_in[i];
        }
    }
    float* out = (float*)d_out;

    k_norm_init<<<256, 256>>>(refm, srcm);
    k1_batch<<<NB, 256>>>(score, refp, srcp);
    k3_gather<<<K3B, 256>>>(refp, srcp);
    k45<<<NB, 256>>>(out);
}

// round 13
// speedup vs baseline: 3.7729x; 3.7729x over previous
#include <cuda_runtime.h>
#include <math.h>

#define NB 512
#define NN 128
#define CORR_LIM 2048
#define CAND_CAP (NB * 3 * NN)
#define NEG_INF -3e38f
#define NBINS_A 2048
#define BIAS_A  0x3D00
#define BINBUF_CAP 65536
#define K3B 64

// ---------------- device scratch ----------------
__device__ float        g_cand_val[CAND_CAP];
__device__ int          g_cand_idx[CAND_CAP];
__device__ int          g_cand_cnt;
__device__ __align__(16) unsigned int g_histA[NBINS_A];
__device__ int          g_bin;
__device__ int          g_G16;
__device__ int          g_kk;
__device__ int          g_gt_ctr;
__device__ float        g_binval[BINBUF_CAP];
__device__ int          g_binidx[BINBUF_CAP];
__device__ int          g_bincnt;
__device__ float        g_localT[NB * 12];
__device__ int          g_pc[NB];
__device__ int          g_best_key;
__device__ float        g_sel_score[CORR_LIM];
__device__ float        g_sel_src[CORR_LIM * 3];
__device__ float        g_sel_ref[CORR_LIM * 3];
__device__ int          g_k2done, g_k3done, g_k4done;
__device__ unsigned char g_refm[NB * NN];
__device__ unsigned char g_srcm[NB * NN];

// ---------------- f32 Kabsch ----------------
__device__ inline float det3f(const float* M) {
    return M[0]*(M[4]*M[8]-M[5]*M[7])
         - M[1]*(M[3]*M[8]-M[5]*M[6])
         + M[2]*(M[3]*M[7]-M[4]*M[6]);
}

__device__ void jacobi3f(float A[9], float V[9]) {
    for (int i = 0; i < 9; i++) V[i] = (i % 4 == 0) ? 1.0f : 0.0f;
    float fro = fabsf(A[0]) + fabsf(A[4]) + fabsf(A[8]) + 1e-30f;
    for (int sweep = 0; sweep < 10; sweep++) {
        float off = fabsf(A[1]) + fabsf(A[2]) + fabsf(A[5]);
        if (off < fro * 1e-7f + 1e-35f) break;
        for (int pq = 0; pq < 3; pq++) {
            int p = (pq == 2) ? 1 : 0;
            int q = (pq == 0) ? 1 : 2;
            float apq = A[p*3+q];
            if (fabsf(apq) < 1e-35f) continue;
            float theta = (A[q*3+q] - A[p*3+p]) / (2.0f * apq);
            float tt = ((theta >= 0.0f) ? 1.0f : -1.0f) / (fabsf(theta) + sqrtf(1.0f + theta*theta));
            float c = rsqrtf(1.0f + tt*tt);
            float s = tt * c;
            for (int k = 0; k < 3; k++) {
                float akp = A[k*3+p], akq = A[k*3+q];
                A[k*3+p] = c*akp - s*akq;
                A[k*3+q] = s*akp + c*akq;
            }
            for (int k = 0; k < 3; k++) {
                float apk = A[p*3+k], aqk = A[q*3+k];
                A[p*3+k] = c*apk - s*aqk;
                A[q*3+k] = s*apk + c*aqk;
            }
            for (int k = 0; k < 3; k++) {
                float vkp = V[k*3+p], vkq = V[k*3+q];
                V[k*3+p] = c*vkp - s*vkq;
                V[k*3+q] = s*vkp + c*vkq;
            }
        }
    }
}

__device__ void kabschf(const float H[9], float R[9]) {
    float A[9];
    for (int i = 0; i < 3; i++)
        for (int j = 0; j < 3; j++)
            A[i*3+j] = H[0+i]*H[0+j] + H[3+i]*H[3+j] + H[6+i]*H[6+j];

    float V[9];
    jacobi3f(A, V);
    float e0 = A[0], e1 = A[4], e2 = A[8];
    int o0 = 0, o1 = 1, o2 = 2;
    float t; int ti;
    if (e0 < e1) { t = e0; e0 = e1; e1 = t; ti = o0; o0 = o1; o1 = ti; }
    if (e0 < e2) { t = e0; e0 = e2; e2 = t; ti = o0; o0 = o2; o2 = ti; }
    if (e1 < e2) { t = e1; e1 = e2; e2 = t; ti = o1; o1 = o2; o2 = ti; }
    float Vs[9];
    int ord[3] = {o0, o1, o2};
    for (int r = 0; r < 3; r++)
        for (int k = 0; k < 3; k++)
            Vs[r*3+k] = V[r*3+ord[k]];

    float u[3][3];
    for (int i = 0; i < 2; i++)
        for (int r = 0; r < 3; r++)
            u[i][r] = H[r*3+0]*Vs[0*3+i] + H[r*3+1]*Vs[1*3+i] + H[r*3+2]*Vs[2*3+i];
    float n0 = sqrtf(u[0][0]*u[0][0] + u[0][1]*u[0][1] + u[0][2]*u[0][2]) + 1e-30f;
    for (int r = 0; r < 3; r++) u[0][r] /= n0;
    float dp = u[1][0]*u[0][0] + u[1][1]*u[0][1] + u[1][2]*u[0][2];
    for (int r = 0; r < 3; r++) u[1][r] -= dp * u[0][r];
    float n1 = sqrtf(u[1][0]*u[1][0] + u[1][1]*u[1][1] + u[1][2]*u[1][2]) + 1e-30f;
    for (int r = 0; r < 3; r++) u[1][r] /= n1;
    u[2][0] = u[0][1]*u[1][2] - u[0][2]*u[1][1];
    u[2][1] = u[0][2]*u[1][0] - u[0][0]*u[1][2];
    u[2][2] = u[0][0]*u[1][1] - u[0][1]*u[1][0];

    float d = (det3f(Vs) >= 0.0f) ? 1.0f : -1.0f;
    for (int i = 0; i < 3; i++)
        for (int j = 0; j < 3; j++)
            R[i*3+j] = Vs[i*3+0]*u[0][j] + Vs[i*3+1]*u[1][j] + Vs[i*3+2]*d*u[2][j];
}

__device__ void solveTf(const float* P, float R[9], float tv[3]) {
    float denom = P[0] + 1e-5f;
    float sc[3] = {P[1]/denom, P[2]/denom, P[3]/denom};
    float rc[3] = {P[4]/denom, P[5]/denom, P[6]/denom};
    float W = P[0] / denom;
    float H[9];
    for (int c = 0; c < 3; c++)
        for (int d = 0; d < 3; d++)
            H[c*3+d] = P[7 + c*3 + d] / denom + (W - 2.0f) * sc[c] * rc[d];
    kabschf(H, R);
    for (int i = 0; i < 3; i++)
        tv[i] = rc[i] - (R[i*3+0]*sc[0] + R[i*3+1]*sc[1] + R[i*3+2]*sc[2]);
}

// ---------------- branchless sorted-triple ops ----------------
__device__ __forceinline__ void ins3(float& c1, float& c2, float& c3, float v) {
    float t1 = fmaxf(c1, v),  d1 = fminf(c1, v);
    float t2 = fmaxf(c2, d1), d2 = fminf(c2, d1);
    c3 = fmaxf(c3, d2); c2 = t2; c1 = t1;
}
__device__ __forceinline__ void merge3(float& a1, float& a2, float& a3,
                                       float b1, float b2, float b3) {
    float c1 = fmaxf(a1, b1);
    float p  = fminf(a1, b1);
    float q  = fmaxf(a2, b2);
    float r  = fminf(a2, b2);
    float c2 = fmaxf(p, q);
    float c3 = fmaxf(fminf(p, q), fmaxf(r, fmaxf(a3, b3)));
    a1 = c1; a2 = c2; a3 = c3;
}

// ---------------- mask handling ----------------
__device__ inline unsigned char fetch_mask(const void* p, int i, int ty) {
    switch (ty) {
        case 0:  return ((const unsigned char*)p)[i] != 0;
        case 1:  return ((const int*)p)[i] != 0;
        case 2:  return ((const unsigned int*)p)[i] != 0;
        default: return ((const unsigned short*)p)[i] != 0;
    }
}

__device__ int detect_mask_type(const unsigned char* p, int t, int* cnts) {
    int l3 = 0, l1 = 0, o1 = 0;
    #pragma unroll
    for (int j = 0; j < 4; j++) {
        int i = t * 4 + j;
        unsigned char bch = p[i];
        int m = i & 3;
        if (bch == 0x3F) { if (m == 3) l3++; else if (m == 1) l1++; }
        if (bch == 0x01 && (i & 1)) o1++;
    }
    if (l3) atomicAdd(&cnts[0], l3);
    if (l1) atomicAdd(&cnts[1], l1);
    if (o1) atomicAdd(&cnts[2], o1);
    __syncthreads();
    if (cnts[1] > 8)      return 3;   // bf16
    else if (cnts[0] > 8) return 2;   // f32
    else if (cnts[2] > 8) return 0;   // u8/bool
    return 1;                          // i32
}

__global__ void k_norm_init(const void* m0, const void* m1) {
    __shared__ int s_cnts[6];
    int t = threadIdx.x;
    int i = blockIdx.x * blockDim.x + t;
    if (t < 6) s_cnts[t] = 0;
    __syncthreads();
    int tyr = detect_mask_type((const unsigned char*)m0, t, &s_cnts[0]);
    int tys = detect_mask_type((const unsigned char*)m1, t, &s_cnts[3]);

    if (i < NBINS_A) g_histA[i] = 0u;
    if (i < CORR_LIM) g_sel_score[i] = 0.0f;
    if (i == 0) {
        g_cand_cnt = 0; g_gt_ctr = 0; g_bincnt = 0;
        g_best_key = 0; g_bin = -1;   g_G16 = 0;  g_kk = 0;
        g_k2done = 0;   g_k3done = 0; g_k4done = 0;
    }
    if (i < NB * NN) {
        g_refm[i] = fetch_mask(m0, i, tyr);
        g_srcm[i] = fetch_mask(m1, i, tys);
    }
}

// -------- two-phase cooperative descending k-select over NBINS bins --------
template<int NBINS>
__device__ void find_binT(const unsigned int* hist, int k,
                          int* out_bin, int* out_above, int* out_rem)
{
    const int CH = NBINS / 256;
    __shared__ unsigned int wsum[8];
    __shared__ unsigned int woff[8];
    __shared__ int s_tb;
    __shared__ unsigned int s_excl;
    int t = threadIdx.x, lane = t & 31, w = t >> 5;

    int base = NBINS - CH * (t + 1);
    unsigned int sum = 0;
    const uint4* hv = (const uint4*)(hist + base);
    #pragma unroll 2
    for (int j = 0; j < CH / 4; j++) {
        uint4 u = hv[j];
        sum += u.x + u.y + u.z + u.w;
    }
    unsigned int sc = sum;
    #pragma unroll
    for (int off = 1; off < 32; off <<= 1) {
        unsigned int v = __shfl_up_sync(0xffffffffu, sc, off);
        if (lane >= off) sc += v;
    }
    if (lane == 31) wsum[w] = sc;
    __syncthreads();
    if (t == 0) {
        unsigned int acc = 0;
        #pragma unroll
        for (int j = 0; j < 8; j++) { woff[j] = acc; acc += wsum[j]; }
    }
    __syncthreads();
    unsigned int incl = sc + woff[w];
    unsigned int excl = incl - sum;
    if (incl >= (unsigned int)k && excl < (unsigned int)k) { s_tb = t; s_excl = excl; }
    __syncthreads();

    int tb = s_tb;
    unsigned int excl_c = s_excl;
    int chunk_top = NBINS - 1 - CH * tb;
    unsigned int h2 = (t < CH) ? hist[chunk_top - t] : 0u;
    unsigned int sc2 = h2;
    #pragma unroll
    for (int off = 1; off < 32; off <<= 1) {
        unsigned int v = __shfl_up_sync(0xffffffffu, sc2, off);
        if (lane >= off) sc2 += v;
    }
    __syncthreads();
    if (lane == 31) wsum[w] = sc2;
    __syncthreads();
    if (t == 0) {
        unsigned int acc = 0;
        #pragma unroll
        for (int j = 0; j < 8; j++) { woff[j] = acc; acc += wsum[j]; }
    }
    __syncthreads();
    unsigned int incl2 = excl_c + sc2 + woff[w];
    unsigned int excl2 = incl2 - h2;
    if (t < CH && incl2 >= (unsigned int)k && excl2 < (unsigned int)k) {
        *out_bin = chunk_top - t;
        *out_above = (int)excl2;
        *out_rem = k - (int)excl2;
    }
}

// ------ cooperative descending k-select over 256 smem bins (1 bin/thread) ----
__device__ void find256(const unsigned int* h, int k, int* out_bin, int* out_above)
{
    __shared__ unsigned int wsum2[8];
    __shared__ unsigned int woff2[8];
    int t = threadIdx.x, lane = t & 31, w = t >> 5;
    unsigned int val = h[255 - t];
    unsigned int sc = val;
    #pragma unroll
    for (int off = 1; off < 32; off <<= 1) {
        unsigned int v = __shfl_up_sync(0xffffffffu, sc, off);
        if (lane >= off) sc += v;
    }
    if (lane == 31) wsum2[w] = sc;
    __syncthreads();
    if (t == 0) {
        unsigned int acc = 0;
        #pragma unroll
        for (int j = 0; j < 8; j++) { woff2[j] = acc; acc += wsum2[j]; }
    }
    __syncthreads();
    unsigned int incl = sc + woff2[w];
    unsigned int excl = incl - val;
    if (incl >= (unsigned int)k && excl < (unsigned int)k) {
        *out_bin = 255 - t;
        *out_above = (int)excl;
    }
    __syncthreads();
}

// ---------------- k1: single-read fused per-batch kernel ----------------
__global__ void __launch_bounds__(256)
k1_batch(const float* __restrict__ score,
         const float* __restrict__ refp,
         const float* __restrict__ srcp)
{
    __shared__ float colpart[8][NN][3];
    __shared__ float colth[NN];
    __shared__ float candv[NN * 4];
    __shared__ int   candcol[NN * 4];
    __shared__ int   candc[NN];
    __shared__ unsigned char s_srcm[NN], s_refm[NN];
    __shared__ float wred[8][17];
    __shared__ int   wcnt[8];
    __shared__ int   s_base;

    int b = blockIdx.x, t = threadIdx.x;
    int w = t >> 5, lane = t & 31;
    const float* Sb = score + (size_t)b * (NN * NN);

    if (t < NN) { s_srcm[t] = g_srcm[b*NN + t]; s_refm[t] = g_refm[b*NN + t]; }
    if (lane < 16) candc[w * 16 + lane] = 0;
    __syncwarp();

    float c1x = NEG_INF, c2x = NEG_INF, c3x = NEG_INF;
    float c1y = NEG_INF, c2y = NEG_INF, c3y = NEG_INF;
    float c1z = NEG_INF, c2z = NEG_INF, c3z = NEG_INF;
    float c1w = NEG_INF, c2w = NEG_INF, c3w = NEG_INF;

    #pragma unroll 1
    for (int i = 0; i < 16; i++) {
        int r = (w << 4) + i;
        float4 v4 = *(const float4*)(Sb + r * NN + lane * 4);

        ins3(c1x, c2x, c3x, v4.x);
        ins3(c1y, c2y, c3y, v4.y);
        ins3(c1z, c2z, c3z, v4.z);
        ins3(c1w, c2w, c3w, v4.w);

        float s1 = fmaxf(v4.x, v4.y), s2 = fminf(v4.x, v4.y);
        float s3 = fmaxf(v4.z, v4.w), s4 = fminf(v4.z, v4.w);
        float a1 = fmaxf(s1, s3),     m  = fminf(s1, s3);
        float tq = fmaxf(s2, s4),     bo = fminf(s2, s4);
        float a2 = fmaxf(m, tq);
        float a3 = fmaxf(fminf(m, tq), bo);

        #pragma unroll
        for (int off = 16; off; off >>= 1) {
            float b1 = __shfl_xor_sync(0xffffffffu, a1, off);
            float b2 = __shfl_xor_sync(0xffffffffu, a2, off);
            float b3 = __shfl_xor_sync(0xffffffffu, a3, off);
            merge3(a1, a2, a3, b1, b2, b3);
        }

        float vv[4] = {v4.x, v4.y, v4.z, v4.w};
        #pragma unroll
        for (int j = 0; j < 4; j++) {
            if (vv[j] >= a3) {
                int pos = atomicAdd(&candc[r], 1);
                if (pos < 4) {
                    candv[r*4 + pos]   = vv[j];
                    candcol[r*4 + pos] = lane * 4 + j;
                }
            }
        }
    }
    {
        int cbase = lane * 4;
        colpart[w][cbase+0][0] = c1x; colpart[w][cbase+0][1] = c2x; colpart[w][cbase+0][2] = c3x;
        colpart[w][cbase+1][0] = c1y; colpart[w][cbase+1][1] = c2y; colpart[w][cbase+1][2] = c3y;
        colpart[w][cbase+2][0] = c1z; colpart[w][cbase+2][1] = c2z; colpart[w][cbase+2][2] = c3z;
        colpart[w][cbase+3][0] = c1w; colpart[w][cbase+3][1] = c2w; colpart[w][cbase+3][2] = c3w;
    }
    __syncthreads();

    if (t < NN) {
        float m1 = colpart[0][t][0], m2 = colpart[0][t][1], m3 = colpart[0][t][2];
        #pragma unroll
        for (int w2 = 1; w2 < 8; w2++)
            merge3(m1, m2, m3, colpart[w2][t][0], colpart[w2][t][1], colpart[w2][t][2]);
        colth[t] = m3;
    }
    __syncthreads();

    bool  ok[2];
    float ev[2];
    int   rr[2], cs2[2];
    int myc = 0;
    #pragma unroll
    for (int k2 = 0; k2 < 2; k2++) {
        int idx = t + k2 * 256;
        int r = idx >> 2, kk = idx & 3;
        bool good = false; float e = 0.0f; int ss = 0;
        int cc = candc[r]; if (cc > 4) cc = 4;
        if (kk < cc && s_refm[r]) {
            float v = candv[idx];
            ss = candcol[idx];
            if (v >= colth[ss] && s_srcm[ss]) {
                e = expf(v);
                if (e > 0.05f) good = true;
            }
        }
        ok[k2] = good; ev[k2] = e; rr[k2] = r; cs2[k2] = ss;
        if (good) myc++;
    }

    int pfx = myc;
    #pragma unroll
    for (int off = 1; off < 32; off <<= 1) {
        int nv = __shfl_up_sync(0xffffffffu, pfx, off);
        if (lane >= off) pfx += nv;
    }
    if (lane == 31) wcnt[w] = pfx;
    __syncthreads();
    if (t == 0) {
        int tot = 0;
        for (int w2 = 0; w2 < 8; w2++) { int c = wcnt[w2]; wcnt[w2] = tot; tot += c; }
        s_base = tot ? atomicAdd(&g_cand_cnt, tot) : 0;
    }
    __syncthreads();
    int pos = s_base + wcnt[w] + (pfx - myc);

    float P[16];
    #pragma unroll
    for (int j = 0; j < 16; j++) P[j] = 0.0f;
    #pragma unroll
    for (int k2 = 0; k2 < 2; k2++) {
        if (!ok[k2]) continue;
        float e = ev[k2];
        int r = rr[k2], ss = cs2[k2];
        g_cand_val[pos] = e;
        g_cand_idx[pos] = (b << 14) | (r << 7) | ss;
        pos++;
        float sx = srcp[(b*NN + ss)*3 + 0];
        float sy = srcp[(b*NN + ss)*3 + 1];
        float sz = srcp[(b*NN + ss)*3 + 2];
        float rx = refp[(b*NN + r)*3 + 0];
        float ry = refp[(b*NN + r)*3 + 1];
        float rz = refp[(b*NN + r)*3 + 2];
        P[0] += e;
        P[1] += e*sx; P[2] += e*sy; P[3] += e*sz;
        P[4] += e*rx; P[5] += e*ry; P[6] += e*rz;
        P[7]  += e*sx*rx; P[8]  += e*sx*ry; P[9]  += e*sx*rz;
        P[10] += e*sy*rx; P[11] += e*sy*ry; P[12] += e*sy*rz;
        P[13] += e*sz*rx; P[14] += e*sz*ry; P[15] += e*sz*rz;
    }

    #pragma unroll
    for (int j = 0; j < 16; j++) {
        float v = P[j];
        #pragma unroll
        for (int off = 16; off; off >>= 1) v += __shfl_xor_sync(0xffffffffu, v, off);
        if (lane == 0) wred[w][j] = v;
    }
    {
        int c = myc;
        #pragma unroll
        for (int off = 16; off; off >>= 1) c += __shfl_xor_sync(0xffffffffu, c, off);
        if (lane == 0) wred[w][16] = (float)c;
    }
    __syncthreads();

    if (t == 0) {
        float Pf[16]; int cnt = 0;
        for (int j = 0; j < 16; j++) {
            float acc = 0.0f;
            for (int w2 = 0; w2 < 8; w2++) acc += wred[w2][j];
            Pf[j] = acc;
        }
        for (int w2 = 0; w2 < 8; w2++) cnt += (int)wred[w2][16];
        float R[9], tv[3];
        solveTf(Pf, R, tv);
        for (int j = 0; j < 9; j++) g_localT[b*12 + j] = R[j];
        for (int j = 0; j < 3; j++) g_localT[b*12 + 9 + j] = tv[j];
        g_pc[b] = cnt;
    }
}

// ------- k2a: smem histogram (warp-dedup) + last-block level-1 find -------
__global__ void __launch_bounds__(256)
k2a_hist()
{
    __shared__ unsigned int h[NBINS_A];
    __shared__ int s_last;
    int M = g_cand_cnt; if (M > CAND_CAP) M = CAND_CAP;
    int t = threadIdx.x;
    if (M > CORR_LIM) {
        for (int i = t; i < NBINS_A; i += 256) h[i] = 0u;
        __syncthreads();
        for (int i = blockIdx.x * 256 + t; i < M; i += gridDim.x * 256) {
            unsigned int v = __float_as_uint(g_cand_val[i]);
            int bb = (int)(v >> 16) - BIAS_A;
            bb = bb < 0 ? 0 : (bb > NBINS_A-1 ? NBINS_A-1 : bb);
            unsigned int am = __activemask();
            unsigned int mm = __match_any_sync(am, bb);
            if ((t & 31) == __ffs(mm) - 1)
                atomicAdd(&h[bb], (unsigned int)__popc(mm));
        }
        __syncthreads();
        for (int i = t; i < NBINS_A; i += 256)
            if (h[i]) atomicAdd(&g_histA[i], h[i]);
    }
    if (t == 0) {
        __threadfence();
        s_last = (atomicAdd(&g_k2done, 1) == (int)gridDim.x - 1);
    }
    __syncthreads();
    if (s_last && M > CORR_LIM)
        find_binT<NBINS_A>(g_histA, CORR_LIM, &g_bin, &g_G16, &g_kk);
}

// ------ k3: gather winners (grid-stride, warp-agg) + last-block select ------
__global__ void __launch_bounds__(256)
k3_gather(const float* __restrict__ refp, const float* __restrict__ srcp)
{
    __shared__ int s_last;
    int M = g_cand_cnt;
    if (M > CAND_CAP) M = CAND_CAP;
    int t = threadIdx.x, lane = t & 31;
    int bin = g_bin;

    for (int base = blockIdx.x * 256; base < M; base += K3B * 256) {
        int i = base + t;
        bool valid = (i < M);
        float v = 0.0f; int bb = -1;
        if (valid) {
            v = g_cand_val[i];
            bb = (int)(__float_as_uint(v) >> 16) - BIAS_A;
            bb = bb < 0 ? 0 : (bb > NBINS_A-1 ? NBINS_A-1 : bb);
        }

        bool win = valid && (bin < 0 || bb > bin);
        {
            unsigned int wm = __ballot_sync(0xffffffffu, win);
            if (wm) {
                int leader = __ffs(wm) - 1;
                int sbase = 0;
                if (lane == leader) sbase = atomicAdd(&g_gt_ctr, __popc(wm));
                sbase = __shfl_sync(0xffffffffu, sbase, leader);
                if (win) {
                    int slot = sbase + __popc(wm & ((1u << lane) - 1u));
                    if (slot < CORR_LIM) {
                        int idx = g_cand_idx[i];
                        int b = idx >> 14, r = (idx >> 7) & 127, s = idx & 127;
                        g_sel_score[slot] = v;
                        g_sel_src[slot*3+0] = srcp[(b*NN + s)*3 + 0];
                        g_sel_src[slot*3+1] = srcp[(b*NN + s)*3 + 1];
                        g_sel_src[slot*3+2] = srcp[(b*NN + s)*3 + 2];
                        g_sel_ref[slot*3+0] = refp[(b*NN + r)*3 + 0];
                        g_sel_ref[slot*3+1] = refp[(b*NN + r)*3 + 1];
                        g_sel_ref[slot*3+2] = refp[(b*NN + r)*3 + 2];
                    }
                }
            }
        }
        bool eq = valid && (bin >= 0) && (bb == bin);
        {
            unsigned int wm = __ballot_sync(0xffffffffu, eq);
            if (wm) {
                int leader = __ffs(wm) - 1;
                int sbase = 0;
                if (lane == leader) sbase = atomicAdd(&g_bincnt, __popc(wm));
                sbase = __shfl_sync(0xffffffffu, sbase, leader);
                if (eq) {
                    int j = sbase + __popc(wm & ((1u << lane) - 1u));
                    if (j < BINBUF_CAP) {
                        g_binval[j] = v;
                        g_binidx[j] = g_cand_idx[i];
                    }
                }
            }
        }
    }

    if (t == 0) {
        __threadfence();
        s_last = (atomicAdd(&g_k3done, 1) == K3B - 1);
    }
    __syncthreads();
    if (!s_last || bin < 0) return;

    // ---- last block: exact top-kk within the boundary bin (two 256-bin
    //      smem passes over the low 16 bits) ----
    __shared__ unsigned int hh[256];
    __shared__ int s_sub1, s_above1, s_sub2, s_above2;
    __shared__ int ctrA, ctrB;
    int B = atomicAdd(&g_bincnt, 0); if (B > BINBUF_CAP) B = BINBUF_CAP;
    int kk = g_kk, G16 = g_G16;
    if (t == 0) { ctrA = 0; ctrB = 0; }

    hh[t] = 0u;
    __syncthreads();
    for (int q = t; q < B; q += 256) {
        unsigned int b1 = (__float_as_uint(__ldcg(&g_binval[q])) >> 8) & 0xFFu;
        unsigned int am = __activemask();
        unsigned int mm = __match_any_sync(am, b1);
        if ((t & 31) == __ffs(mm) - 1)
            atomicAdd(&hh[b1], (unsigned int)__popc(mm));
    }
    __syncthreads();
    find256(hh, kk, &s_sub1, &s_above1);
    __syncthreads();
    int SUB1 = s_sub1, ABOVE1 = s_above1;
    int rem1 = kk - ABOVE1;

    hh[t] = 0u;
    __syncthreads();
    for (int q = t; q < B; q += 256) {
        unsigned int lo = __float_as_uint(__ldcg(&g_binval[q])) & 0xFFFFu;
        if ((int)(lo >> 8) == SUB1) {
            unsigned int b2 = lo & 0xFFu;
            unsigned int am = __activemask();
            unsigned int mm = __match_any_sync(am, b2);
            if ((t & 31) == __ffs(mm) - 1)
                atomicAdd(&hh[b2], (unsigned int)__popc(mm));
        }
    }
    __syncthreads();
    find256(hh, rem1, &s_sub2, &s_above2);
    __syncthreads();
    int TH = (SUB1 << 8) | s_sub2;
    int LA = ABOVE1 + s_above2;
    int nties = rem1 - s_above2;

    for (int q = t; q < B; q += 256) {
        float vv = __ldcg(&g_binval[q]);
        int low = (int)(__float_as_uint(vv) & 0xFFFFu);
        int slot = -1;
        if (low > TH) {
            slot = G16 + atomicAdd(&ctrA, 1);
        } else if (low == TH) {
            int e = atomicAdd(&ctrB, 1);
            if (e < nties) slot = G16 + LA + e;
        }
        if (slot >= 0 && slot < CORR_LIM) {
            int idx = __ldcg(&g_binidx[q]);
            int b = idx >> 14, r = (idx >> 7) & 127, s = idx & 127;
            g_sel_score[slot] = vv;
            g_sel_src[slot*3+0] = srcp[(b*NN + s)*3 + 0];
            g_sel_src[slot*3+1] = srcp[(b*NN + s)*3 + 1];
            g_sel_src[slot*3+2] = srcp[(b*NN + s)*3 + 2];
            g_sel_ref[slot*3+0] = refp[(b*NN + r)*3 + 0];
            g_sel_ref[slot*3+1] = refp[(b*NN + r)*3 + 1];
            g_sel_ref[slot*3+2] = refp[(b*NN + r)*3 + 2];
        }
    }
}

// ------- k45: inlier counts + packed argmax + last-block refine -------
__global__ void __launch_bounds__(256)
k45(float* __restrict__ out)
{
    __shared__ int rc_[8];
    __shared__ int s_last;
    int p = blockIdx.x, t = threadIdx.x;
    int w = t >> 5, lane = t & 31;
    {
        const float* LT = &g_localT[p * 12];
        float R0 = LT[0], R1 = LT[1], R2 = LT[2];
        float R3 = LT[3], R4 = LT[4], R5 = LT[5];
        float R6 = LT[6], R7 = LT[7], R8 = LT[8];
        float t0 = LT[9], t1 = LT[10], t2 = LT[11];
        int c = 0;
        for (int i = t; i < CORR_LIM; i += 256) {
            float sv = g_sel_score[i];
            if (sv <= 0.0f) continue;
            float sx = g_sel_src[i*3+0], sy = g_sel_src[i*3+1], sz = g_sel_src[i*3+2];
            float rx = g_sel_ref[i*3+0], ry = g_sel_ref[i*3+1], rz = g_sel_ref[i*3+2];
            float ax = R0*sx + R1*sy + R2*sz + t0;
            float ay = R3*sx + R4*sy + R5*sz + t1;
            float az = R6*sx + R7*sy + R8*sz + t2;
            float dx = rx - ax, dy = ry - ay, dz = rz - az;
            if (dx*dx + dy*dy + dz*dz < 0.01f) c++;
        }
        #pragma unroll
        for (int off = 16; off; off >>= 1) c += __shfl_xor_sync(0xffffffffu, c, off);
        if (lane == 0) rc_[w] = c;
        __syncthreads();
        if (t == 0) {
            int total = 0;
            for (int j = 0; j < 8; j++) total += rc_[j];
            int cnt = (g_pc[p] >= 3) ? total : -1;
            int key = ((cnt + 1) << 16) | (NB - 1 - p);
            atomicMax(&g_best_key, key);
            __threadfence();
            s_last = (atomicAdd(&g_k4done, 1) == NB - 1);
        }
        __syncthreads();
    }
    if (!s_last) return;

    __shared__ float red[8][16];
    __shared__ float Tr[9], Tt[3];
    if (t == 0) {
        int bk = atomicAdd(&g_best_key, 0);
        int bb = NB - 1 - (bk & 0xFFFF);
        for (int j = 0; j < 9; j++) Tr[j] = g_localT[bb*12 + j];
        for (int j = 0; j < 3; j++) Tt[j] = g_localT[bb*12 + 9 + j];
    }
    __syncthreads();

    float lsv[8], lsx[8], lsy[8], lsz[8], lrx[8], lry[8], lrz[8];
    #pragma unroll
    for (int j = 0; j < 8; j++) {
        int i = t + j * 256;
        lsv[j] = g_sel_score[i];
        lsx[j] = g_sel_src[i*3+0]; lsy[j] = g_sel_src[i*3+1]; lsz[j] = g_sel_src[i*3+2];
        lrx[j] = g_sel_ref[i*3+0]; lry[j] = g_sel_ref[i*3+1]; lrz[j] = g_sel_ref[i*3+2];
    }

    unsigned int prev_mask = 0u;
    for (int it = 0; it < 5; it++) {
        float P[16];
        #pragma unroll
        for (int j = 0; j < 16; j++) P[j] = 0.0f;
        unsigned int cur_mask = 0u;
        #pragma unroll
        for (int j = 0; j < 8; j++) {
            float sv = lsv[j];
            if (sv <= 0.0f) continue;
            float sx = lsx[j], sy = lsy[j], sz = lsz[j];
            float rx = lrx[j], ry = lry[j], rz = lrz[j];
            float ax = Tr[0]*sx + Tr[1]*sy + Tr[2]*sz + Tt[0];
            float ay = Tr[3]*sx + Tr[4]*sy + Tr[5]*sz + Tt[1];
            float az = Tr[6]*sx + Tr[7]*sy + Tr[8]*sz + Tt[2];
            float dx = rx - ax, dy = ry - ay, dz = rz - az;
            if (dx*dx + dy*dy + dz*dz < 0.01f) {
                cur_mask |= (1u << j);
                P[0] += sv;
                P[1] += sv*sx; P[2] += sv*sy; P[3] += sv*sz;
                P[4] += sv*rx; P[5] += sv*ry; P[6] += sv*rz;
                P[7]  += sv*sx*rx; P[8]  += sv*sx*ry; P[9]  += sv*sx*rz;
                P[10] += sv*sy*rx; P[11] += sv*sy*ry; P[12] += sv*sy*rz;
                P[13] += sv*sz*rx; P[14] += sv*sz*ry; P[15] += sv*sz*rz;
            }
        }
        int same = __syncthreads_and((it > 0) && (cur_mask == prev_mask));
        if (same) break;
        prev_mask = cur_mask;

        #pragma unroll
        for (int j = 0; j < 16; j++) {
            float v = P[j];
            #pragma unroll
            for (int off = 16; off; off >>= 1) v += __shfl_xor_sync(0xffffffffu, v, off);
            if (lane == 0) red[w][j] = v;
        }
        __syncthreads();
        if (t == 0) {
            float Pf[16];
            for (int j = 0; j < 16; j++) {
                float acc = 0.0f;
                for (int w2 = 0; w2 < 8; w2++) acc += red[w2][j];
                Pf[j] = acc;
            }
            float R[9], tv[3];
            solveTf(Pf, R, tv);
            for (int j = 0; j < 9; j++) Tr[j] = R[j];
            for (int j = 0; j < 3; j++) Tt[j] = tv[j];
        }
        __syncthreads();
    }

    if (t == 0) {
        out[0]  = Tr[0]; out[1]  = Tr[1]; out[2]  = Tr[2]; out[3]  = Tt[0];
        out[4]  = Tr[3]; out[5]  = Tr[4]; out[6]  = Tr[5]; out[7]  = Tt[1];
        out[8]  = Tr[6]; out[9]  = Tr[7]; out[10] = Tr[8]; out[11] = Tt[2];
        out[12] = 0.0f; out[13] = 0.0f; out[14] = 0.0f; out[15] = 1.0f;
    }
}

// ---------------- launch ----------------
extern "C" void kernel_launch(void* const* d_in, const int* in_sizes, int n_in,
                              void* d_out, int out_size)
{
    const float* score = 0;
    const float* refp = 0;  const float* srcp = 0;
    const void*  refm = 0;  const void*  srcm = 0;
    for (int i = 0; i < n_in; i++) {
        int sz = in_sizes[i];
        if (sz == NB * NN * NN) {
            score = (const float*)d_in[i];
        } else if (sz == NB * NN * 3) {
            if (!refp) refp = (const float*)d_in[i];
            else       srcp = (const float*)d_in[i];
        } else if (sz == NB * NN) {
            if (!refm) refm = d_in[i];
            else       srcm = d_in[i];
        }
    }
    float* out = (float*)d_out;

    k_norm_init<<<256, 256>>>(refm, srcm);
    k1_batch<<<NB, 256>>>(score, refp, srcp);
    k2a_hist<<<16, 256>>>();
    k3_gather<<<K3B, 256>>>(refp, srcp);
    k45<<<NB, 256>>>(out);
}

// round 14
// speedup vs baseline: 5.2804x; 1.3995x over previous
#include <cuda_runtime.h>
#include <math.h>

#define NB 512
#define NN 128
#define CORR_LIM 2048
#define CAND_CAP (NB * 3 * NN)
#define NEG_INF -3e38f
#define NBINS_A 2048
#define BIAS_A  0x3D00
#define BINBUF_CAP 196608
#define K3_BLOCKS ((CAND_CAP + 255) / 256)
#define K45_BLOCKS (NB / 4)

// ---------------- device scratch ----------------
__device__ float        g_cand_val[CAND_CAP];
__device__ int          g_cand_idx[CAND_CAP];
__device__ int          g_cand_cnt;
__device__ __align__(16) unsigned int g_histA[NBINS_A];
__device__ int          g_bin;
__device__ int          g_G16;
__device__ int          g_kk;
__device__ int          g_gt_ctr;
__device__ float        g_binval[BINBUF_CAP];
__device__ int          g_binidx[BINBUF_CAP];
__device__ int          g_bincnt;
__device__ float        g_localT[NB * 12];
__device__ int          g_pc[NB];
__device__ int          g_best_key;
__device__ float4       g_selA[CORR_LIM];   // {score, sx, sy, sz}
__device__ float4       g_selB[CORR_LIM];   // {rx, ry, rz, 0}
__device__ int          g_k2done, g_k3done, g_k4done;
__device__ unsigned char g_refm[NB * NN];
__device__ unsigned char g_srcm[NB * NN];

// ---------------- f32 Kabsch ----------------
__device__ inline float det3f(const float* M) {
    return M[0]*(M[4]*M[8]-M[5]*M[7])
         - M[1]*(M[3]*M[8]-M[5]*M[6])
         + M[2]*(M[3]*M[7]-M[4]*M[6]);
}

__device__ void jacobi3f(float A[9], float V[9]) {
    for (int i = 0; i < 9; i++) V[i] = (i % 4 == 0) ? 1.0f : 0.0f;
    float fro = fabsf(A[0]) + fabsf(A[4]) + fabsf(A[8]) + 1e-30f;
    for (int sweep = 0; sweep < 10; sweep++) {
        float off = fabsf(A[1]) + fabsf(A[2]) + fabsf(A[5]);
        if (off < fro * 1e-7f + 1e-35f) break;
        for (int pq = 0; pq < 3; pq++) {
            int p = (pq == 2) ? 1 : 0;
            int q = (pq == 0) ? 1 : 2;
            float apq = A[p*3+q];
            if (fabsf(apq) < 1e-35f) continue;
            float theta = (A[q*3+q] - A[p*3+p]) / (2.0f * apq);
            float tt = ((theta >= 0.0f) ? 1.0f : -1.0f) / (fabsf(theta) + sqrtf(1.0f + theta*theta));
            float c = rsqrtf(1.0f + tt*tt);
            float s = tt * c;
            for (int k = 0; k < 3; k++) {
                float akp = A[k*3+p], akq = A[k*3+q];
                A[k*3+p] = c*akp - s*akq;
                A[k*3+q] = s*akp + c*akq;
            }
            for (int k = 0; k < 3; k++) {
                float apk = A[p*3+k], aqk = A[q*3+k];
                A[p*3+k] = c*apk - s*aqk;
                A[q*3+k] = s*apk + c*aqk;
            }
            for (int k = 0; k < 3; k++) {
                float vkp = V[k*3+p], vkq = V[k*3+q];
                V[k*3+p] = c*vkp - s*vkq;
                V[k*3+q] = s*vkp + c*vkq;
            }
        }
    }
}

__device__ void kabschf(const float H[9], float R[9]) {
    float A[9];
    for (int i = 0; i < 3; i++)
        for (int j = 0; j < 3; j++)
            A[i*3+j] = H[0+i]*H[0+j] + H[3+i]*H[3+j] + H[6+i]*H[6+j];

    float V[9];
    jacobi3f(A, V);
    float e0 = A[0], e1 = A[4], e2 = A[8];
    int o0 = 0, o1 = 1, o2 = 2;
    float t; int ti;
    if (e0 < e1) { t = e0; e0 = e1; e1 = t; ti = o0; o0 = o1; o1 = ti; }
    if (e0 < e2) { t = e0; e0 = e2; e2 = t; ti = o0; o0 = o2; o2 = ti; }
    if (e1 < e2) { t = e1; e1 = e2; e2 = t; ti = o1; o1 = o2; o2 = ti; }
    float Vs[9];
    int ord[3] = {o0, o1, o2};
    for (int r = 0; r < 3; r++)
        for (int k = 0; k < 3; k++)
            Vs[r*3+k] = V[r*3+ord[k]];

    float u[3][3];
    for (int i = 0; i < 2; i++)
        for (int r = 0; r < 3; r++)
            u[i][r] = H[r*3+0]*Vs[0*3+i] + H[r*3+1]*Vs[1*3+i] + H[r*3+2]*Vs[2*3+i];
    float n0 = sqrtf(u[0][0]*u[0][0] + u[0][1]*u[0][1] + u[0][2]*u[0][2]) + 1e-30f;
    for (int r = 0; r < 3; r++) u[0][r] /= n0;
    float dp = u[1][0]*u[0][0] + u[1][1]*u[0][1] + u[1][2]*u[0][2];
    for (int r = 0; r < 3; r++) u[1][r] -= dp * u[0][r];
    float n1 = sqrtf(u[1][0]*u[1][0] + u[1][1]*u[1][1] + u[1][2]*u[1][2]) + 1e-30f;
    for (int r = 0; r < 3; r++) u[1][r] /= n1;
    u[2][0] = u[0][1]*u[1][2] - u[0][2]*u[1][1];
    u[2][1] = u[0][2]*u[1][0] - u[0][0]*u[1][2];
    u[2][2] = u[0][0]*u[1][1] - u[0][1]*u[1][0];

    float d = (det3f(Vs) >= 0.0f) ? 1.0f : -1.0f;
    for (int i = 0; i < 3; i++)
        for (int j = 0; j < 3; j++)
            R[i*3+j] = Vs[i*3+0]*u[0][j] + Vs[i*3+1]*u[1][j] + Vs[i*3+2]*d*u[2][j];
}

__device__ void solveTf(const float* P, float R[9], float tv[3]) {
    float denom = P[0] + 1e-5f;
    float sc[3] = {P[1]/denom, P[2]/denom, P[3]/denom};
    float rc[3] = {P[4]/denom, P[5]/denom, P[6]/denom};
    float W = P[0] / denom;
    float H[9];
    for (int c = 0; c < 3; c++)
        for (int d = 0; d < 3; d++)
            H[c*3+d] = P[7 + c*3 + d] / denom + (W - 2.0f) * sc[c] * rc[d];
    kabschf(H, R);
    for (int i = 0; i < 3; i++)
        tv[i] = rc[i] - (R[i*3+0]*sc[0] + R[i*3+1]*sc[1] + R[i*3+2]*sc[2]);
}

// ---------------- branchless sorted-triple ops ----------------
__device__ __forceinline__ void ins3(float& c1, float& c2, float& c3, float v) {
    float t1 = fmaxf(c1, v),  d1 = fminf(c1, v);
    float t2 = fmaxf(c2, d1), d2 = fminf(c2, d1);
    c3 = fmaxf(c3, d2); c2 = t2; c1 = t1;
}
__device__ __forceinline__ void merge3(float& a1, float& a2, float& a3,
                                       float b1, float b2, float b3) {
    float c1 = fmaxf(a1, b1);
    float p  = fminf(a1, b1);
    float q  = fmaxf(a2, b2);
    float r  = fminf(a2, b2);
    float c2 = fmaxf(p, q);
    float c3 = fmaxf(fminf(p, q), fmaxf(r, fmaxf(a3, b3)));
    a1 = c1; a2 = c2; a3 = c3;
}

// ---------------- mask handling ----------------
__device__ inline unsigned char fetch_mask(const void* p, int i, int ty) {
    switch (ty) {
        case 0:  return ((const unsigned char*)p)[i] != 0;
        case 1:  return ((const int*)p)[i] != 0;
        case 2:  return ((const unsigned int*)p)[i] != 0;
        default: return ((const unsigned short*)p)[i] != 0;
    }
}

__device__ int detect_mask_type(const unsigned char* p, int t, int* cnts) {
    int l3 = 0, l1 = 0, o1 = 0;
    #pragma unroll
    for (int j = 0; j < 4; j++) {
        int i = t * 4 + j;
        unsigned char bch = p[i];
        int m = i & 3;
        if (bch == 0x3F) { if (m == 3) l3++; else if (m == 1) l1++; }
        if (bch == 0x01 && (i & 1)) o1++;
    }
    if (l3) atomicAdd(&cnts[0], l3);
    if (l1) atomicAdd(&cnts[1], l1);
    if (o1) atomicAdd(&cnts[2], o1);
    __syncthreads();
    if (cnts[1] > 8)      return 3;
    else if (cnts[0] > 8) return 2;
    else if (cnts[2] > 8) return 0;
    return 1;
}

__global__ void k_norm_init(const void* m0, const void* m1) {
    __shared__ int s_cnts[6];
    int t = threadIdx.x;
    int i = blockIdx.x * blockDim.x + t;
    if (t < 6) s_cnts[t] = 0;
    __syncthreads();
    int tyr = detect_mask_type((const unsigned char*)m0, t, &s_cnts[0]);
    int tys = detect_mask_type((const unsigned char*)m1, t, &s_cnts[3]);

    if (i < NBINS_A) g_histA[i] = 0u;
    if (i < CORR_LIM) {
        g_selA[i] = make_float4(0.0f, 0.0f, 0.0f, 0.0f);
        g_selB[i] = make_float4(0.0f, 0.0f, 0.0f, 0.0f);
    }
    if (i == 0) {
        g_cand_cnt = 0; g_gt_ctr = 0; g_bincnt = 0;
        g_best_key = 0; g_bin = -1;   g_G16 = 0;  g_kk = 0;
        g_k2done = 0;   g_k3done = 0; g_k4done = 0;
    }
    if (i < NB * NN) {
        g_refm[i] = fetch_mask(m0, i, tyr);
        g_srcm[i] = fetch_mask(m1, i, tys);
    }
}

// -------- two-phase cooperative descending k-select over NBINS bins --------
template<int NBINS>
__device__ void find_binT(const unsigned int* hist, int k,
                          int* out_bin, int* out_above, int* out_rem)
{
    const int CH = NBINS / 256;
    __shared__ unsigned int wsum[8];
    __shared__ unsigned int woff[8];
    __shared__ int s_tb;
    __shared__ unsigned int s_excl;
    int t = threadIdx.x, lane = t & 31, w = t >> 5;

    int base = NBINS - CH * (t + 1);
    unsigned int sum = 0;
    const uint4* hv = (const uint4*)(hist + base);
    #pragma unroll 2
    for (int j = 0; j < CH / 4; j++) {
        uint4 u = hv[j];
        sum += u.x + u.y + u.z + u.w;
    }
    unsigned int sc = sum;
    #pragma unroll
    for (int off = 1; off < 32; off <<= 1) {
        unsigned int v = __shfl_up_sync(0xffffffffu, sc, off);
        if (lane >= off) sc += v;
    }
    if (lane == 31) wsum[w] = sc;
    __syncthreads();
    if (t == 0) {
        unsigned int acc = 0;
        #pragma unroll
        for (int j = 0; j < 8; j++) { woff[j] = acc; acc += wsum[j]; }
    }
    __syncthreads();
    unsigned int incl = sc + woff[w];
    unsigned int excl = incl - sum;
    if (incl >= (unsigned int)k && excl < (unsigned int)k) { s_tb = t; s_excl = excl; }
    __syncthreads();

    int tb = s_tb;
    unsigned int excl_c = s_excl;
    int chunk_top = NBINS - 1 - CH * tb;
    unsigned int h2 = (t < CH) ? hist[chunk_top - t] : 0u;
    unsigned int sc2 = h2;
    #pragma unroll
    for (int off = 1; off < 32; off <<= 1) {
        unsigned int v = __shfl_up_sync(0xffffffffu, sc2, off);
        if (lane >= off) sc2 += v;
    }
    __syncthreads();
    if (lane == 31) wsum[w] = sc2;
    __syncthreads();
    if (t == 0) {
        unsigned int acc = 0;
        #pragma unroll
        for (int j = 0; j < 8; j++) { woff[j] = acc; acc += wsum[j]; }
    }
    __syncthreads();
    unsigned int incl2 = excl_c + sc2 + woff[w];
    unsigned int excl2 = incl2 - h2;
    if (t < CH && incl2 >= (unsigned int)k && excl2 < (unsigned int)k) {
        *out_bin = chunk_top - t;
        *out_above = (int)excl2;
        *out_rem = k - (int)excl2;
    }
}

// ------ cooperative descending k-select over 256 smem bins (1 bin/thread) ----
__device__ void find256(const unsigned int* h, int k, int* out_bin, int* out_above)
{
    __shared__ unsigned int wsum2[8];
    __shared__ unsigned int woff2[8];
    int t = threadIdx.x, lane = t & 31, w = t >> 5;
    unsigned int val = h[255 - t];
    unsigned int sc = val;
    #pragma unroll
    for (int off = 1; off < 32; off <<= 1) {
        unsigned int v = __shfl_up_sync(0xffffffffu, sc, off);
        if (lane >= off) sc += v;
    }
    if (lane == 31) wsum2[w] = sc;
    __syncthreads();
    if (t == 0) {
        unsigned int acc = 0;
        #pragma unroll
        for (int j = 0; j < 8; j++) { woff2[j] = acc; acc += wsum2[j]; }
    }
    __syncthreads();
    unsigned int incl = sc + woff2[w];
    unsigned int excl = incl - val;
    if (incl >= (unsigned int)k && excl < (unsigned int)k) {
        *out_bin = 255 - t;
        *out_above = (int)excl;
    }
    __syncthreads();
}

// ---------------- k1: single-read fused per-batch kernel ----------------
__global__ void __launch_bounds__(256)
k1_batch(const float* __restrict__ score,
         const float* __restrict__ refp,
         const float* __restrict__ srcp)
{
    __shared__ float colpart[8][NN][3];
    __shared__ float colth[NN];
    __shared__ float candv[NN * 4];
    __shared__ int   candcol[NN * 4];
    __shared__ int   candc[NN];
    __shared__ unsigned char s_srcm[NN], s_refm[NN];
    __shared__ float wred[8][17];
    __shared__ int   wcnt[8];
    __shared__ int   s_base;

    int b = blockIdx.x, t = threadIdx.x;
    int w = t >> 5, lane = t & 31;
    const float* Sb = score + (size_t)b * (NN * NN);

    if (t < NN) { s_srcm[t] = g_srcm[b*NN + t]; s_refm[t] = g_refm[b*NN + t]; }
    if (lane < 16) candc[w * 16 + lane] = 0;
    __syncwarp();

    float c1x = NEG_INF, c2x = NEG_INF, c3x = NEG_INF;
    float c1y = NEG_INF, c2y = NEG_INF, c3y = NEG_INF;
    float c1z = NEG_INF, c2z = NEG_INF, c3z = NEG_INF;
    float c1w = NEG_INF, c2w = NEG_INF, c3w = NEG_INF;

    #pragma unroll 1
    for (int i = 0; i < 16; i++) {
        int r = (w << 4) + i;
        float4 v4 = *(const float4*)(Sb + r * NN + lane * 4);

        ins3(c1x, c2x, c3x, v4.x);
        ins3(c1y, c2y, c3y, v4.y);
        ins3(c1z, c2z, c3z, v4.z);
        ins3(c1w, c2w, c3w, v4.w);

        float s1 = fmaxf(v4.x, v4.y), s2 = fminf(v4.x, v4.y);
        float s3 = fmaxf(v4.z, v4.w), s4 = fminf(v4.z, v4.w);
        float a1 = fmaxf(s1, s3),     m  = fminf(s1, s3);
        float tq = fmaxf(s2, s4),     bo = fminf(s2, s4);
        float a2 = fmaxf(m, tq);
        float a3 = fmaxf(fminf(m, tq), bo);

        #pragma unroll
        for (int off = 16; off; off >>= 1) {
            float b1 = __shfl_xor_sync(0xffffffffu, a1, off);
            float b2 = __shfl_xor_sync(0xffffffffu, a2, off);
            float b3 = __shfl_xor_sync(0xffffffffu, a3, off);
            merge3(a1, a2, a3, b1, b2, b3);
        }

        float vv[4] = {v4.x, v4.y, v4.z, v4.w};
        #pragma unroll
        for (int j = 0; j < 4; j++) {
            if (vv[j] >= a3) {
                int pos = atomicAdd(&candc[r], 1);
                if (pos < 4) {
                    candv[r*4 + pos]   = vv[j];
                    candcol[r*4 + pos] = lane * 4 + j;
                }
            }
        }
    }
    {
        int cbase = lane * 4;
        colpart[w][cbase+0][0] = c1x; colpart[w][cbase+0][1] = c2x; colpart[w][cbase+0][2] = c3x;
        colpart[w][cbase+1][0] = c1y; colpart[w][cbase+1][1] = c2y; colpart[w][cbase+1][2] = c3y;
        colpart[w][cbase+2][0] = c1z; colpart[w][cbase+2][1] = c2z; colpart[w][cbase+2][2] = c3z;
        colpart[w][cbase+3][0] = c1w; colpart[w][cbase+3][1] = c2w; colpart[w][cbase+3][2] = c3w;
    }
    __syncthreads();

    if (t < NN) {
        float m1 = colpart[0][t][0], m2 = colpart[0][t][1], m3 = colpart[0][t][2];
        #pragma unroll
        for (int w2 = 1; w2 < 8; w2++)
            merge3(m1, m2, m3, colpart[w2][t][0], colpart[w2][t][1], colpart[w2][t][2]);
        colth[t] = m3;
    }
    __syncthreads();

    bool  ok[2];
    float ev[2];
    int   rr[2], cs2[2];
    int myc = 0;
    #pragma unroll
    for (int k2 = 0; k2 < 2; k2++) {
        int idx = t + k2 * 256;
        int r = idx >> 2, kk = idx & 3;
        bool good = false; float e = 0.0f; int ss = 0;
        int cc = candc[r]; if (cc > 4) cc = 4;
        if (kk < cc && s_refm[r]) {
            float v = candv[idx];
            ss = candcol[idx];
            if (v >= colth[ss] && s_srcm[ss]) {
                e = expf(v);
                if (e > 0.05f) good = true;
            }
        }
        ok[k2] = good; ev[k2] = e; rr[k2] = r; cs2[k2] = ss;
        if (good) myc++;
    }

    int pfx = myc;
    #pragma unroll
    for (int off = 1; off < 32; off <<= 1) {
        int nv = __shfl_up_sync(0xffffffffu, pfx, off);
        if (lane >= off) pfx += nv;
    }
    if (lane == 31) wcnt[w] = pfx;
    __syncthreads();
    if (t == 0) {
        int tot = 0;
        for (int w2 = 0; w2 < 8; w2++) { int c = wcnt[w2]; wcnt[w2] = tot; tot += c; }
        s_base = tot ? atomicAdd(&g_cand_cnt, tot) : 0;
    }
    __syncthreads();
    int pos = s_base + wcnt[w] + (pfx - myc);

    float P[16];
    #pragma unroll
    for (int j = 0; j < 16; j++) P[j] = 0.0f;
    #pragma unroll
    for (int k2 = 0; k2 < 2; k2++) {
        if (!ok[k2]) continue;
        float e = ev[k2];
        int r = rr[k2], ss = cs2[k2];
        g_cand_val[pos] = e;
        g_cand_idx[pos] = (b << 14) | (r << 7) | ss;
        pos++;
        float sx = srcp[(b*NN + ss)*3 + 0];
        float sy = srcp[(b*NN + ss)*3 + 1];
        float sz = srcp[(b*NN + ss)*3 + 2];
        float rx = refp[(b*NN + r)*3 + 0];
        float ry = refp[(b*NN + r)*3 + 1];
        float rz = refp[(b*NN + r)*3 + 2];
        P[0] += e;
        P[1] += e*sx; P[2] += e*sy; P[3] += e*sz;
        P[4] += e*rx; P[5] += e*ry; P[6] += e*rz;
        P[7]  += e*sx*rx; P[8]  += e*sx*ry; P[9]  += e*sx*rz;
        P[10] += e*sy*rx; P[11] += e*sy*ry; P[12] += e*sy*rz;
        P[13] += e*sz*rx; P[14] += e*sz*ry; P[15] += e*sz*rz;
    }

    #pragma unroll
    for (int j = 0; j < 16; j++) {
        float v = P[j];
        #pragma unroll
        for (int off = 16; off; off >>= 1) v += __shfl_xor_sync(0xffffffffu, v, off);
        if (lane == 0) wred[w][j] = v;
    }
    {
        int c = myc;
        #pragma unroll
        for (int off = 16; off; off >>= 1) c += __shfl_xor_sync(0xffffffffu, c, off);
        if (lane == 0) wred[w][16] = (float)c;
    }
    __syncthreads();

    if (t == 0) {
        float Pf[16]; int cnt = 0;
        for (int j = 0; j < 16; j++) {
            float acc = 0.0f;
            for (int w2 = 0; w2 < 8; w2++) acc += wred[w2][j];
            Pf[j] = acc;
        }
        for (int w2 = 0; w2 < 8; w2++) cnt += (int)wred[w2][16];
        float R[9], tv[3];
        solveTf(Pf, R, tv);
        for (int j = 0; j < 9; j++) g_localT[b*12 + j] = R[j];
        for (int j = 0; j < 3; j++) g_localT[b*12 + 9 + j] = tv[j];
        g_pc[b] = cnt;
    }
}

// ------- k2a: smem histogram (warp-dedup) + last-block level-1 find -------
__global__ void __launch_bounds__(256)
k2a_hist()
{
    __shared__ unsigned int h[NBINS_A];
    __shared__ int s_last;
    int M = g_cand_cnt; if (M > CAND_CAP) M = CAND_CAP;
    int t = threadIdx.x;
    if (M > CORR_LIM) {
        for (int i = t; i < NBINS_A; i += 256) h[i] = 0u;
        __syncthreads();
        for (int i = blockIdx.x * 256 + t; i < M; i += gridDim.x * 256) {
            unsigned int v = __float_as_uint(g_cand_val[i]);
            int bb = (int)(v >> 16) - BIAS_A;
            bb = bb < 0 ? 0 : (bb > NBINS_A-1 ? NBINS_A-1 : bb);
            unsigned int am = __activemask();
            unsigned int mm = __match_any_sync(am, bb);
            if ((t & 31) == __ffs(mm) - 1)
                atomicAdd(&h[bb], (unsigned int)__popc(mm));
        }
        __syncthreads();
        for (int i = t; i < NBINS_A; i += 256)
            if (h[i]) atomicAdd(&g_histA[i], h[i]);
    }
    if (t == 0) {
        __threadfence();
        s_last = (atomicAdd(&g_k2done, 1) == (int)gridDim.x - 1);
    }
    __syncthreads();
    if (s_last && M > CORR_LIM)
        find_binT<NBINS_A>(g_histA, CORR_LIM, &g_bin, &g_G16, &g_kk);
}

// ------ k3: gather winners (1 item/thread, warp-agg) + last-block select ----
__global__ void __launch_bounds__(256)
k3_gather(const float* __restrict__ refp, const float* __restrict__ srcp)
{
    __shared__ int s_last;
    int M = g_cand_cnt;
    if (M > CAND_CAP) M = CAND_CAP;
    int t = threadIdx.x, lane = t & 31;
    int i = blockIdx.x * 256 + t;
    int bin = g_bin;

    bool valid = (i < M);
    float v = 0.0f; int bb = -1;
    if (valid) {
        v = g_cand_val[i];
        bb = (int)(__float_as_uint(v) >> 16) - BIAS_A;
        bb = bb < 0 ? 0 : (bb > NBINS_A-1 ? NBINS_A-1 : bb);
    }

    bool win = valid && (bin < 0 || bb > bin);
    {
        unsigned int wm = __ballot_sync(0xffffffffu, win);
        if (wm) {
            int leader = __ffs(wm) - 1;
            int sbase = 0;
            if (lane == leader) sbase = atomicAdd(&g_gt_ctr, __popc(wm));
            sbase = __shfl_sync(0xffffffffu, sbase, leader);
            if (win) {
                int slot = sbase + __popc(wm & ((1u << lane) - 1u));
                if (slot < CORR_LIM) {
                    int idx = g_cand_idx[i];
                    int b = idx >> 14, r = (idx >> 7) & 127, s = idx & 127;
                    const float* sp = srcp + (b*NN + s)*3;
                    const float* rp = refp + (b*NN + r)*3;
                    g_selA[slot] = make_float4(v, sp[0], sp[1], sp[2]);
                    g_selB[slot] = make_float4(rp[0], rp[1], rp[2], 0.0f);
                }
            }
        }
    }
    bool eq = valid && (bin >= 0) && (bb == bin);
    {
        unsigned int wm = __ballot_sync(0xffffffffu, eq);
        if (wm) {
            int leader = __ffs(wm) - 1;
            int sbase = 0;
            if (lane == leader) sbase = atomicAdd(&g_bincnt, __popc(wm));
            sbase = __shfl_sync(0xffffffffu, sbase, leader);
            if (eq) {
                int j = sbase + __popc(wm & ((1u << lane) - 1u));
                if (j < BINBUF_CAP) {
                    g_binval[j] = v;
                    g_binidx[j] = g_cand_idx[i];
                }
            }
        }
    }

    if (t == 0) {
        __threadfence();
        s_last = (atomicAdd(&g_k3done, 1) == K3_BLOCKS - 1);
    }
    __syncthreads();
    if (!s_last || bin < 0) return;

    // ---- last block: exact top-kk within boundary bin (two 256-bin passes) --
    __shared__ unsigned int hh[256];
    __shared__ int s_sub1, s_above1, s_sub2, s_above2;
    __shared__ int ctrA, ctrB;
    int B = atomicAdd(&g_bincnt, 0); if (B > BINBUF_CAP) B = BINBUF_CAP;
    int kk = g_kk, G16 = g_G16;
    if (t == 0) { ctrA = 0; ctrB = 0; }

    hh[t] = 0u;
    __syncthreads();
    for (int q = t; q < B; q += 256) {
        unsigned int b1 = (__float_as_uint(__ldcg(&g_binval[q])) >> 8) & 0xFFu;
        unsigned int am = __activemask();
        unsigned int mm = __match_any_sync(am, b1);
        if ((t & 31) == __ffs(mm) - 1)
            atomicAdd(&hh[b1], (unsigned int)__popc(mm));
    }
    __syncthreads();
    find256(hh, kk, &s_sub1, &s_above1);
    __syncthreads();
    int SUB1 = s_sub1, ABOVE1 = s_above1;
    int rem1 = kk - ABOVE1;

    hh[t] = 0u;
    __syncthreads();
    for (int q = t; q < B; q += 256) {
        unsigned int lo = __float_as_uint(__ldcg(&g_binval[q])) & 0xFFFFu;
        if ((int)(lo >> 8) == SUB1) {
            unsigned int b2 = lo & 0xFFu;
            unsigned int am = __activemask();
            unsigned int mm = __match_any_sync(am, b2);
            if ((t & 31) == __ffs(mm) - 1)
                atomicAdd(&hh[b2], (unsigned int)__popc(mm));
        }
    }
    __syncthreads();
    find256(hh, rem1, &s_sub2, &s_above2);
    __syncthreads();
    int TH = (SUB1 << 8) | s_sub2;
    int LA = ABOVE1 + s_above2;
    int nties = rem1 - s_above2;

    for (int q = t; q < B; q += 256) {
        float vv = __ldcg(&g_binval[q]);
        int low = (int)(__float_as_uint(vv) & 0xFFFFu);
        int slot = -1;
        if (low > TH) {
            slot = G16 + atomicAdd(&ctrA, 1);
        } else if (low == TH) {
            int e = atomicAdd(&ctrB, 1);
            if (e < nties) slot = G16 + LA + e;
        }
        if (slot >= 0 && slot < CORR_LIM) {
            int idx = __ldcg(&g_binidx[q]);
            int b = idx >> 14, r = (idx >> 7) & 127, s = idx & 127;
            const float* sp = srcp + (b*NN + s)*3;
            const float* rp = refp + (b*NN + r)*3;
            g_selA[slot] = make_float4(vv, sp[0], sp[1], sp[2]);
            g_selB[slot] = make_float4(rp[0], rp[1], rp[2], 0.0f);
        }
    }
}

// --- k45: 4 transforms/block, items loaded once; last-block refine ---------
__global__ void __launch_bounds__(256)
k45(float* __restrict__ out)
{
    __shared__ int rc_[8];
    __shared__ int s_last;
    int t = threadIdx.x;
    int w = t >> 5, lane = t & 31;

    // load this thread's 8 items once
    float4 A[8], Bv[8];
    #pragma unroll
    for (int j = 0; j < 8; j++) {
        int i = t + j * 256;
        A[j]  = g_selA[i];
        Bv[j] = g_selB[i];
    }

    #pragma unroll 1
    for (int pp = 0; pp < 4; pp++) {
        int p = blockIdx.x * 4 + pp;
        const float* LT = &g_localT[p * 12];
        float R0 = LT[0], R1 = LT[1], R2 = LT[2];
        float R3 = LT[3], R4 = LT[4], R5 = LT[5];
        float R6 = LT[6], R7 = LT[7], R8 = LT[8];
        float t0 = LT[9], t1 = LT[10], t2 = LT[11];
        int c = 0;
        #pragma unroll
        for (int j = 0; j < 8; j++) {
            float sv = A[j].x;
            if (sv <= 0.0f) continue;
            float sx = A[j].y, sy = A[j].z, sz = A[j].w;
            float ax = R0*sx + R1*sy + R2*sz + t0;
            float ay = R3*sx + R4*sy + R5*sz + t1;
            float az = R6*sx + R7*sy + R8*sz + t2;
            float dx = Bv[j].x - ax, dy = Bv[j].y - ay, dz = Bv[j].z - az;
            if (dx*dx + dy*dy + dz*dz < 0.01f) c++;
        }
        #pragma unroll
        for (int off = 16; off; off >>= 1) c += __shfl_xor_sync(0xffffffffu, c, off);
        if (lane == 0) rc_[w] = c;
        __syncthreads();
        if (t == 0) {
            int total = 0;
            for (int j = 0; j < 8; j++) total += rc_[j];
            int cnt = (g_pc[p] >= 3) ? total : -1;
            int key = ((cnt + 1) << 16) | (NB - 1 - p);
            atomicMax(&g_best_key, key);
        }
        __syncthreads();
    }

    if (t == 0) {
        __threadfence();
        s_last = (atomicAdd(&g_k4done, 1) == K45_BLOCKS - 1);
    }
    __syncthreads();
    if (!s_last) return;

    // ---- refine (last block only) ----
    __shared__ float red[8][16];
    __shared__ float Tr[9], Tt[3];
    if (t == 0) {
        int bk = atomicAdd(&g_best_key, 0);
        int bb = NB - 1 - (bk & 0xFFFF);
        for (int j = 0; j < 9; j++) Tr[j] = g_localT[bb*12 + j];
        for (int j = 0; j < 3; j++) Tt[j] = g_localT[bb*12 + 9 + j];
    }
    __syncthreads();

    unsigned int prev_mask = 0u;
    for (int it = 0; it < 5; it++) {
        float P[16];
        #pragma unroll
        for (int j = 0; j < 16; j++) P[j] = 0.0f;
        unsigned int cur_mask = 0u;
        #pragma unroll
        for (int j = 0; j < 8; j++) {
            float sv = A[j].x;
            if (sv <= 0.0f) continue;
            float sx = A[j].y, sy = A[j].z, sz = A[j].w;
            float rx = Bv[j].x, ry = Bv[j].y, rz = Bv[j].z;
            float ax = Tr[0]*sx + Tr[1]*sy + Tr[2]*sz + Tt[0];
            float ay = Tr[3]*sx + Tr[4]*sy + Tr[5]*sz + Tt[1];
            float az = Tr[6]*sx + Tr[7]*sy + Tr[8]*sz + Tt[2];
            float dx = rx - ax, dy = ry - ay, dz = rz - az;
            if (dx*dx + dy*dy + dz*dz < 0.01f) {
                cur_mask |= (1u << j);
                P[0] += sv;
                P[1] += sv*sx; P[2] += sv*sy; P[3] += sv*sz;
                P[4] += sv*rx; P[5] += sv*ry; P[6] += sv*rz;
                P[7]  += sv*sx*rx; P[8]  += sv*sx*ry; P[9]  += sv*sx*rz;
                P[10] += sv*sy*rx; P[11] += sv*sy*ry; P[12] += sv*sy*rz;
                P[13] += sv*sz*rx; P[14] += sv*sz*ry; P[15] += sv*sz*rz;
            }
        }
        int same = __syncthreads_and((it > 0) && (cur_mask == prev_mask));
        if (same) break;
        prev_mask = cur_mask;

        #pragma unroll
        for (int j = 0; j < 16; j++) {
            float v = P[j];
            #pragma unroll
            for (int off = 16; off; off >>= 1) v += __shfl_xor_sync(0xffffffffu, v, off);
            if (lane == 0) red[w][j] = v;
        }
        __syncthreads();
        if (t == 0) {
            float Pf[16];
            for (int j = 0; j < 16; j++) {
                float acc = 0.0f;
                for (int w2 = 0; w2 < 8; w2++) acc += red[w2][j];
                Pf[j] = acc;
            }
            float R[9], tv[3];
            solveTf(Pf, R, tv);
            for (int j = 0; j < 9; j++) Tr[j] = R[j];
            for (int j = 0; j < 3; j++) Tt[j] = tv[j];
        }
        __syncthreads();
    }

    if (t == 0) {
        out[0]  = Tr[0]; out[1]  = Tr[1]; out[2]  = Tr[2]; out[3]  = Tt[0];
        out[4]  = Tr[3]; out[5]  = Tr[4]; out[6]  = Tr[5]; out[7]  = Tt[1];
        out[8]  = Tr[6]; out[9]  = Tr[7]; out[10] = Tr[8]; out[11] = Tt[2];
        out[12] = 0.0f; out[13] = 0.0f; out[14] = 0.0f; out[15] = 1.0f;
    }
}

// ---------------- launch ----------------
extern "C" void kernel_launch(void* const* d_in, const int* in_sizes, int n_in,
                              void* d_out, int out_size)
{
    const float* score = 0;
    const float* refp = 0;  const float* srcp = 0;
    const void*  refm = 0;  const void*  srcm = 0;
    for (int i = 0; i < n_in; i++) {
        int sz = in_sizes[i];
        if (sz == NB * NN * NN) {
            score = (const float*)d_in[i];
        } else if (sz == NB * NN * 3) {
            if (!refp) refp = (const float*)d_in[i];
            else       srcp = (const float*)d_in[i];
        } else if (sz == NB * NN) {
            if (!refm) refm = d_in[i];
            else       srcm = d_in[i];
        }
    }
    float* out = (float*)d_out;

    k_norm_init<<<256, 256>>>(refm, srcm);
    k1_batch<<<NB, 256>>>(score, refp, srcp);
    k2a_hist<<<64, 256>>>();
    k3_gather<<<K3_BLOCKS, 256>>>(refp, srcp);
    k45<<<K45_BLOCKS, 256>>>(out);
}